// round 1
// baseline (speedup 1.0000x reference)
#include <cuda_runtime.h>

#define EPSF 1e-5f

// Scratch (device globals; no allocations allowed)
static __device__ float g_xs[6291456];   // LIF1 spikes (T,B,C,H,W)
static __device__ float g_y [3145728];   // conv+BN output (16,768,16,16)
static __device__ float g_sp3[6291456];  // LIF3 spikes (T,B,C,H,W)

// ---- packed fp32x2 helpers (Blackwell FFMA2 via PTX) ----
__device__ __forceinline__ unsigned long long pk2(float lo, float hi) {
    unsigned long long r;
    asm("mov.b64 %0, {%1,%2};" : "=l"(r) : "f"(lo), "f"(hi));
    return r;
}
__device__ __forceinline__ void upk2(unsigned long long v, float& lo, float& hi) {
    asm("mov.b64 {%0,%1}, %2;" : "=f"(lo), "=f"(hi) : "l"(v));
}
__device__ __forceinline__ unsigned long long ffma2(unsigned long long a,
                                                    unsigned long long b,
                                                    unsigned long long c) {
    unsigned long long d;
    asm("fma.rn.f32x2 %0, %1, %2, %3;" : "=l"(d) : "l"(a), "l"(b), "l"(c));
    return d;
}

// ============================================================
// Kernel A: LIF over T on x -> spikes g_xs
// ============================================================
__global__ void __launch_bounds__(256) lif1_kernel(const float* __restrict__ x) {
    const int S = 4 * 384 * 1024;  // B*C*H*W
    int i = blockIdx.x * blockDim.x + threadIdx.x;
    if (i >= S) return;
    float v = 0.0f;
#pragma unroll
    for (int t = 0; t < 4; t++) {
        v = 0.5f * (v + x[(size_t)t * S + i]);
        bool s = (v >= 1.0f);
        g_xs[(size_t)t * S + i] = s ? 1.0f : 0.0f;
        v = s ? 0.0f : v;
    }
}

// ============================================================
// Kernel B: stride-2 2x2 conv as GEMM (768 x 256, K=1536) + BN1
// grid: 16 imgs x 12 o-tiles x 4 p-tiles = 768 blocks, 256 threads
// ============================================================
__global__ void __launch_bounds__(256) conv_bn_kernel(
    const float* __restrict__ Wc, const float* __restrict__ g1,
    const float* __restrict__ b1)
{
    __shared__ __align__(16) float As[16 * 68];
    __shared__ __align__(16) float Bs[16 * 68];
    const int bx = blockIdx.x;
    const int pt = bx & 3;
    const int ot = (bx >> 2) % 12;
    const int img = bx / 48;
    const int tid = threadIdx.x;
    const int tx = tid & 15, ty = tid >> 4;
    const int obase = ot * 64, pbase = pt * 64;

    unsigned long long acc[4][2];
#pragma unroll
    for (int r = 0; r < 4; r++) { acc[r][0] = 0ull; acc[r][1] = 0ull; }

    const float* xsb = g_xs + (size_t)img * 384 * 1024;

    for (int kc = 0; kc < 1536; kc += 16) {
#pragma unroll
        for (int r = 0; r < 4; r++) {
            int e = tid + 256 * r;
            int o = e >> 4, k = e & 15;
            As[k * 68 + o] = Wc[(size_t)(obase + o) * 1536 + kc + k];
        }
#pragma unroll
        for (int r = 0; r < 4; r++) {
            int e = tid + 256 * r;
            int p = e & 63, k = e >> 6;
            int kk = kc + k;
            int c = kk >> 2, kh = (kk >> 1) & 1, kw = kk & 1;
            int pp = pbase + p;
            int ii = pp >> 4, jj = pp & 15;
            Bs[k * 68 + p] = xsb[(c * 32 + 2 * ii + kh) * 32 + 2 * jj + kw];
        }
        __syncthreads();
#pragma unroll
        for (int k = 0; k < 16; k++) {
            float4 a4 = *(const float4*)&As[k * 68 + ty * 4];
            ulonglong2 b2 = *(const ulonglong2*)&Bs[k * 68 + tx * 4];
            unsigned long long ar;
            ar = pk2(a4.x, a4.x); acc[0][0] = ffma2(ar, b2.x, acc[0][0]); acc[0][1] = ffma2(ar, b2.y, acc[0][1]);
            ar = pk2(a4.y, a4.y); acc[1][0] = ffma2(ar, b2.x, acc[1][0]); acc[1][1] = ffma2(ar, b2.y, acc[1][1]);
            ar = pk2(a4.z, a4.z); acc[2][0] = ffma2(ar, b2.x, acc[2][0]); acc[2][1] = ffma2(ar, b2.y, acc[2][1]);
            ar = pk2(a4.w, a4.w); acc[3][0] = ffma2(ar, b2.x, acc[3][0]); acc[3][1] = ffma2(ar, b2.y, acc[3][1]);
        }
        __syncthreads();
    }
    const float rs = rsqrtf(1.0f + EPSF);
#pragma unroll
    for (int r = 0; r < 4; r++) {
        int o = obase + ty * 4 + r;
        float bn = g1[o] * rs;
        float bt = b1[o];
        float v0, v1, v2, v3;
        upk2(acc[r][0], v0, v1); upk2(acc[r][1], v2, v3);
        float4 ov = make_float4(v0 * bn + bt, v1 * bn + bt, v2 * bn + bt, v3 * bn + bt);
        *(float4*)&g_y[((size_t)img * 768 + o) * 256 + pbase + tx * 4] = ov;
    }
}

// ============================================================
// Kernel C: fused attn GEMM -> LIF2 -> out GEMM -> LIF3
// grid: b(4) x h(12) x mtile(32) = 1536 blocks, 256 threads
// attn (256 x 1024) never hits HBM; LIF states in registers over T.
// ============================================================
__global__ void __launch_bounds__(256) attn_fused_kernel(
    const float* __restrict__ frx, const float* __restrict__ fra)
{
    extern __shared__ __align__(16) float sm[];
    float* y1s = sm;            // [32][256]           = 8192
    float* y2s = sm + 8192;     // [32][260] (pad)     = 8320
    float* xrs = sm + 16512;    // [32][32]            = 1024
    float* ss  = sm + 17536;    // [256][36] (pad)     = 9216   total 26752 floats

    const int bx = blockIdx.x;
    const int mt = bx & 31;
    const int h  = (bx >> 5) % 12;
    const int b  = bx / 384;
    const int tid = threadIdx.x;
    const int dd = tid >> 3;   // GEMM2 role: output row d (0..31)
    const int mg = tid & 7;    // GEMM2 role: m group (4 cols each)

    const float scale1 = rsqrtf(frx[h] * 32.0f);
    const float scale2 = rsqrtf(fra[h] * 256.0f);

    float v2[32];  // LIF2 state for (n=tid, 32 m's)
    float v3[4];   // LIF3 state for (dd, 4 m's)
#pragma unroll
    for (int i = 0; i < 32; i++) v2[i] = 0.0f;
#pragma unroll
    for (int i = 0; i < 4; i++) v3[i] = 0.0f;

    for (int t = 0; t < 4; t++) {
        const int img = t * 4 + b;
        const float* ybase = g_y + ((size_t)img * 768 + h * 64) * 256;
#pragma unroll
        for (int d = 0; d < 32; d++)
            y1s[d * 256 + tid] = ybase[d * 256 + tid] * scale1;
#pragma unroll
        for (int d = 0; d < 32; d++)
            y2s[d * 260 + tid] = ybase[(32 + d) * 256 + tid] * scale2;
        const float* xbase = g_xs + ((size_t)img * 384 + h * 32) * 1024 + mt * 32;
#pragma unroll
        for (int r = 0; r < 4; r++) {
            int e = tid + 256 * r;
            xrs[e] = xbase[(e >> 5) * 1024 + (e & 31)];
        }
        __syncthreads();

        // ---- GEMM1: attn[n, m0..31] = sum_d y1[d,n]*xr[d,m]  (pre-seeded with v2) ----
        unsigned long long acc[16];
#pragma unroll
        for (int i = 0; i < 16; i++) acc[i] = pk2(v2[2 * i], v2[2 * i + 1]);
#pragma unroll 4
        for (int d = 0; d < 32; d++) {
            float a = y1s[d * 256 + tid];
            unsigned long long a2 = pk2(a, a);
            const ulonglong2* xr = (const ulonglong2*)&xrs[d * 32];
#pragma unroll
            for (int q = 0; q < 8; q++) {
                ulonglong2 xv = xr[q];
                acc[2 * q]     = ffma2(a2, xv.x, acc[2 * q]);
                acc[2 * q + 1] = ffma2(a2, xv.y, acc[2 * q + 1]);
            }
        }
        // ---- LIF2: v' = 0.5*(v + attn); spike; reset ----
#pragma unroll
        for (int q = 0; q < 8; q++) {
            float a0, a1, a2f, a3;
            upk2(acc[2 * q], a0, a1);
            upk2(acc[2 * q + 1], a2f, a3);
            a0 *= 0.5f; a1 *= 0.5f; a2f *= 0.5f; a3 *= 0.5f;
            float4 sv;
            sv.x = (a0  >= 1.0f) ? 1.0f : 0.0f; v2[4 * q + 0] = (a0  >= 1.0f) ? 0.0f : a0;
            sv.y = (a1  >= 1.0f) ? 1.0f : 0.0f; v2[4 * q + 1] = (a1  >= 1.0f) ? 0.0f : a1;
            sv.z = (a2f >= 1.0f) ? 1.0f : 0.0f; v2[4 * q + 2] = (a2f >= 1.0f) ? 0.0f : a2f;
            sv.w = (a3  >= 1.0f) ? 1.0f : 0.0f; v2[4 * q + 3] = (a3  >= 1.0f) ? 0.0f : a3;
            *(float4*)&ss[tid * 36 + 4 * q] = sv;
        }
        __syncthreads();

        // ---- GEMM2: out[dd, m] = sum_n y2[dd,n]*s[n,m]  (pre-seeded with v3) ----
        unsigned long long acc2[2];
        acc2[0] = pk2(v3[0], v3[1]);
        acc2[1] = pk2(v3[2], v3[3]);
#pragma unroll 4
        for (int nn = 0; nn < 256; nn += 4) {
            float4 bv = *(const float4*)&y2s[dd * 260 + nn];
            ulonglong2 s0 = *(const ulonglong2*)&ss[(nn + 0) * 36 + mg * 4];
            ulonglong2 s1 = *(const ulonglong2*)&ss[(nn + 1) * 36 + mg * 4];
            ulonglong2 s2 = *(const ulonglong2*)&ss[(nn + 2) * 36 + mg * 4];
            ulonglong2 s3 = *(const ulonglong2*)&ss[(nn + 3) * 36 + mg * 4];
            unsigned long long b2;
            b2 = pk2(bv.x, bv.x); acc2[0] = ffma2(b2, s0.x, acc2[0]); acc2[1] = ffma2(b2, s0.y, acc2[1]);
            b2 = pk2(bv.y, bv.y); acc2[0] = ffma2(b2, s1.x, acc2[0]); acc2[1] = ffma2(b2, s1.y, acc2[1]);
            b2 = pk2(bv.z, bv.z); acc2[0] = ffma2(b2, s2.x, acc2[0]); acc2[1] = ffma2(b2, s2.y, acc2[1]);
            b2 = pk2(bv.w, bv.w); acc2[0] = ffma2(b2, s3.x, acc2[0]); acc2[1] = ffma2(b2, s3.y, acc2[1]);
        }
        // ---- LIF3 ----
        float o0, o1, o2, o3;
        upk2(acc2[0], o0, o1); upk2(acc2[1], o2, o3);
        o0 *= 0.5f; o1 *= 0.5f; o2 *= 0.5f; o3 *= 0.5f;
        float4 so;
        so.x = (o0 >= 1.0f) ? 1.0f : 0.0f; v3[0] = (o0 >= 1.0f) ? 0.0f : o0;
        so.y = (o1 >= 1.0f) ? 1.0f : 0.0f; v3[1] = (o1 >= 1.0f) ? 0.0f : o1;
        so.z = (o2 >= 1.0f) ? 1.0f : 0.0f; v3[2] = (o2 >= 1.0f) ? 0.0f : o2;
        so.w = (o3 >= 1.0f) ? 1.0f : 0.0f; v3[3] = (o3 >= 1.0f) ? 0.0f : o3;
        *(float4*)&g_sp3[((size_t)img * 384 + h * 32 + dd) * 1024 + mt * 32 + mg * 4] = so;
        __syncthreads();
    }
}

// ============================================================
// Kernel D: channel projection GEMM (384x384) + BN2 + residual
// grid: 6 o-tiles x 256 n-tiles = 1536 blocks, 256 threads
// ============================================================
__global__ void __launch_bounds__(256) proj_kernel(
    const float* __restrict__ Wp, const float* __restrict__ g2,
    const float* __restrict__ b2v, const float* __restrict__ x,
    float* __restrict__ out)
{
    __shared__ __align__(16) float As[16 * 68];
    __shared__ __align__(16) float Bs[16 * 68];
    const int bx = blockIdx.x;
    const int nt = bx & 255;
    const int ot = bx >> 8;
    const int tid = threadIdx.x;
    const int tx = tid & 15, ty = tid >> 4;
    const int obase = ot * 64;
    const int nbase = nt * 64;
    const int tb = nbase >> 10;
    const int hw0 = nbase & 1023;
    const float rs = rsqrtf(1.0f + EPSF);

    unsigned long long acc[4][2];
#pragma unroll
    for (int r = 0; r < 4; r++) { acc[r][0] = 0ull; acc[r][1] = 0ull; }

    for (int kc = 0; kc < 384; kc += 16) {
#pragma unroll
        for (int r = 0; r < 4; r++) {
            int e = tid + 256 * r;
            int o = e >> 4, k = e & 15;
            As[k * 68 + o] = Wp[(size_t)(obase + o) * 384 + kc + k] * (g2[obase + o] * rs);
        }
#pragma unroll
        for (int r = 0; r < 4; r++) {
            int e = tid + 256 * r;
            int p = e & 63, k = e >> 6;
            Bs[k * 68 + p] = g_sp3[((size_t)tb * 384 + kc + k) * 1024 + hw0 + p];
        }
        __syncthreads();
#pragma unroll
        for (int k = 0; k < 16; k++) {
            float4 a4 = *(const float4*)&As[k * 68 + ty * 4];
            ulonglong2 b2 = *(const ulonglong2*)&Bs[k * 68 + tx * 4];
            unsigned long long ar;
            ar = pk2(a4.x, a4.x); acc[0][0] = ffma2(ar, b2.x, acc[0][0]); acc[0][1] = ffma2(ar, b2.y, acc[0][1]);
            ar = pk2(a4.y, a4.y); acc[1][0] = ffma2(ar, b2.x, acc[1][0]); acc[1][1] = ffma2(ar, b2.y, acc[1][1]);
            ar = pk2(a4.z, a4.z); acc[2][0] = ffma2(ar, b2.x, acc[2][0]); acc[2][1] = ffma2(ar, b2.y, acc[2][1]);
            ar = pk2(a4.w, a4.w); acc[3][0] = ffma2(ar, b2.x, acc[3][0]); acc[3][1] = ffma2(ar, b2.y, acc[3][1]);
        }
        __syncthreads();
    }
#pragma unroll
    for (int r = 0; r < 4; r++) {
        int o = obase + ty * 4 + r;
        size_t idx = ((size_t)tb * 384 + o) * 1024 + hw0 + tx * 4;
        float4 xv = *(const float4*)&x[idx];
        float bt = b2v[o];
        float v0, v1, v2, v3;
        upk2(acc[r][0], v0, v1); upk2(acc[r][1], v2, v3);
        float4 ov = make_float4(v0 + bt + xv.x, v1 + bt + xv.y,
                                v2 + bt + xv.z, v3 + bt + xv.w);
        *(float4*)&out[idx] = ov;
    }
}

// ============================================================
extern "C" void kernel_launch(void* const* d_in, const int* in_sizes, int n_in,
                              void* d_out, int out_size) {
    const float* x   = (const float*)d_in[0];
    const float* Wc  = (const float*)d_in[1];
    const float* g1  = (const float*)d_in[2];
    const float* b1  = (const float*)d_in[3];
    const float* Wp  = (const float*)d_in[4];
    const float* g2  = (const float*)d_in[5];
    const float* b2  = (const float*)d_in[6];
    const float* frx = (const float*)d_in[7];
    const float* fra = (const float*)d_in[8];
    float* out = (float*)d_out;

    const int smem_attn = 26752 * 4;  // 107,008 B
    cudaFuncSetAttribute(attn_fused_kernel,
                         cudaFuncAttributeMaxDynamicSharedMemorySize, smem_attn);

    lif1_kernel<<<6144, 256>>>(x);
    conv_bn_kernel<<<768, 256>>>(Wc, g1, b1);
    attn_fused_kernel<<<1536, 256, smem_attn>>>(frx, fra);
    proj_kernel<<<1536, 256>>>(Wp, g2, b2, x, out);
}

// round 2
// speedup vs baseline: 1.0833x; 1.0833x over previous
#include <cuda_runtime.h>

#define EPSF 1e-5f

// Scratch (device globals; no allocations allowed)
static __device__ float g_xs[6291456];        // LIF1 spikes (T,B,C,H,W)
static __device__ float g_y [3145728];        // conv+BN output (16,768,16,16)
static __device__ float g_yp[3][3145728];     // conv K-split partials
static __device__ float g_sp3[6291456];       // LIF3 spikes (T,B,C,H,W)

// ---- packed fp32x2 helpers (Blackwell FFMA2 via PTX) ----
__device__ __forceinline__ unsigned long long pk2(float lo, float hi) {
    unsigned long long r;
    asm("mov.b64 %0, {%1,%2};" : "=l"(r) : "f"(lo), "f"(hi));
    return r;
}
__device__ __forceinline__ void upk2(unsigned long long v, float& lo, float& hi) {
    asm("mov.b64 {%0,%1}, %2;" : "=f"(lo), "=f"(hi) : "l"(v));
}
__device__ __forceinline__ unsigned long long ffma2(unsigned long long a,
                                                    unsigned long long b,
                                                    unsigned long long c) {
    unsigned long long d;
    asm("fma.rn.f32x2 %0, %1, %2, %3;" : "=l"(d) : "l"(a), "l"(b), "l"(c));
    return d;
}

// ============================================================
// Kernel A: LIF over T on x -> spikes g_xs
// ============================================================
__global__ void __launch_bounds__(256) lif1_kernel(const float* __restrict__ x) {
    const int S = 4 * 384 * 1024;  // B*C*H*W
    int i = blockIdx.x * blockDim.x + threadIdx.x;
    if (i >= S) return;
    float v = 0.0f;
#pragma unroll
    for (int t = 0; t < 4; t++) {
        v = 0.5f * (v + x[(size_t)t * S + i]);
        bool s = (v >= 1.0f);
        g_xs[(size_t)t * S + i] = s ? 1.0f : 0.0f;
        v = s ? 0.0f : v;
    }
}

// ============================================================
// Kernel B: conv-as-GEMM partials. 128x128 tile, 8x8/thread,
// double-buffered smem, K split 3 ways (512 each).
// grid: 3 ksplit x 16 img x 6 ot x 2 pt = 576 blocks, 256 thr
// ============================================================
__global__ void __launch_bounds__(256, 2) conv_partial_kernel(
    const float* __restrict__ Wc)
{
    __shared__ __align__(16) float As[2][16][128];
    __shared__ __align__(16) float Bs[2][16][128];
    const int bx = blockIdx.x;
    const int ks = bx / 192;
    const int rem = bx % 192;
    const int img = rem / 12;
    const int ot = (rem % 12) >> 1;
    const int pt = rem & 1;
    const int kbase = ks * 512;
    const int tid = threadIdx.x;
    const int tx = tid & 15, ty = tid >> 4;
    const int obase = ot * 128, pbase = pt * 128;
    const int oA = tid & 127, kh2 = tid >> 7;
    const float* xsb = g_xs + (size_t)img * 393216;

    unsigned long long acc[8][4];
#pragma unroll
    for (int r = 0; r < 8; r++)
#pragma unroll
        for (int q = 0; q < 4; q++) acc[r][q] = 0ull;

    auto ldA = [&](int kc, int buf) {
#pragma unroll
        for (int v = 0; v < 2; v++) {
            float4 w = *(const float4*)&Wc[(size_t)(obase + oA) * 1536 + kc + kh2 * 8 + v * 4];
            As[buf][kh2 * 8 + v * 4 + 0][oA] = w.x;
            As[buf][kh2 * 8 + v * 4 + 1][oA] = w.y;
            As[buf][kh2 * 8 + v * 4 + 2][oA] = w.z;
            As[buf][kh2 * 8 + v * 4 + 3][oA] = w.w;
        }
    };
    auto ldB = [&](int kc, int buf) {
#pragma unroll
        for (int r = 0; r < 8; r++) {
            int e = tid + 256 * r;
            int k = e >> 7, p = e & 127;
            int kk = kc + k;
            int c = kk >> 2, kh = (kk >> 1) & 1, kw = kk & 1;
            int pp = pbase + p;
            int ii = pp >> 4, jj = pp & 15;
            Bs[buf][k][p] = xsb[(c * 32 + 2 * ii + kh) * 32 + 2 * jj + kw];
        }
    };

    int buf = 0;
    ldA(kbase, 0); ldB(kbase, 0);
    __syncthreads();
    for (int kc = 0; kc < 512; kc += 16) {
        if (kc + 16 < 512) { ldA(kbase + kc + 16, buf ^ 1); ldB(kbase + kc + 16, buf ^ 1); }
#pragma unroll
        for (int k = 0; k < 16; k++) {
            float4 a0 = *(const float4*)&As[buf][k][ty * 8];
            float4 a1 = *(const float4*)&As[buf][k][ty * 8 + 4];
            ulonglong2 b0 = *(const ulonglong2*)&Bs[buf][k][tx * 8];
            ulonglong2 b1 = *(const ulonglong2*)&Bs[buf][k][tx * 8 + 4];
            float av[8] = {a0.x, a0.y, a0.z, a0.w, a1.x, a1.y, a1.z, a1.w};
#pragma unroll
            for (int r = 0; r < 8; r++) {
                unsigned long long ar = pk2(av[r], av[r]);
                acc[r][0] = ffma2(ar, b0.x, acc[r][0]);
                acc[r][1] = ffma2(ar, b0.y, acc[r][1]);
                acc[r][2] = ffma2(ar, b1.x, acc[r][2]);
                acc[r][3] = ffma2(ar, b1.y, acc[r][3]);
            }
        }
        __syncthreads();
        buf ^= 1;
    }

    float* yo = g_yp[ks] + ((size_t)img * 768 + obase) * 256 + pbase + tx * 8;
#pragma unroll
    for (int r = 0; r < 8; r++) {
        int o = ty * 8 + r;
        float v0, v1, v2, v3, v4, v5, v6, v7;
        upk2(acc[r][0], v0, v1); upk2(acc[r][1], v2, v3);
        upk2(acc[r][2], v4, v5); upk2(acc[r][3], v6, v7);
        *(float4*)(yo + (size_t)o * 256)     = make_float4(v0, v1, v2, v3);
        *(float4*)(yo + (size_t)o * 256 + 4) = make_float4(v4, v5, v6, v7);
    }
}

// ============================================================
// Kernel B2: reduce 3 K-split partials + BN1 -> g_y
// grid: 3072 x 256 covers 786432 float4
// ============================================================
__global__ void __launch_bounds__(256) reduce_bn_kernel(
    const float* __restrict__ g1, const float* __restrict__ b1)
{
    int i4 = blockIdx.x * 256 + threadIdx.x;
    const float4* p0 = (const float4*)g_yp[0];
    const float4* p1 = (const float4*)g_yp[1];
    const float4* p2 = (const float4*)g_yp[2];
    float4 a = p0[i4], b = p1[i4], c = p2[i4];
    int o = (i4 >> 6) % 768;
    const float rs = rsqrtf(1.0f + EPSF);
    float bn = g1[o] * rs, bt = b1[o];
    ((float4*)g_y)[i4] = make_float4(
        (a.x + b.x + c.x) * bn + bt,
        (a.y + b.y + c.y) * bn + bt,
        (a.z + b.z + c.z) * bn + bt,
        (a.w + b.w + c.w) * bn + bt);
}

// ============================================================
// Kernel C: fused attn GEMM -> LIF2 -> out GEMM -> LIF3
// grid: b(4) x h(12) x mtile(32) = 1536 blocks, 256 threads
// ============================================================
__global__ void __launch_bounds__(256, 2) attn_fused_kernel(
    const float* __restrict__ frx, const float* __restrict__ fra)
{
    extern __shared__ __align__(16) float sm[];
    float* y1s = sm;            // [32][256]
    float* y2s = sm + 8192;     // [32][260]
    float* xrs = sm + 16512;    // [32][32]
    float* ss  = sm + 17536;    // [256][36]

    const int bx = blockIdx.x;
    const int mt = bx & 31;
    const int h  = (bx >> 5) % 12;
    const int b  = bx / 384;
    const int tid = threadIdx.x;
    const int dd = tid >> 3;
    const int mg = tid & 7;

    const float scale1 = rsqrtf(frx[h] * 32.0f);
    const float scale2 = rsqrtf(fra[h] * 256.0f);

    float v2[32];
    float v3[4];
#pragma unroll
    for (int i = 0; i < 32; i++) v2[i] = 0.0f;
#pragma unroll
    for (int i = 0; i < 4; i++) v3[i] = 0.0f;

    for (int t = 0; t < 4; t++) {
        const int img = t * 4 + b;
        const float* ybase = g_y + ((size_t)img * 768 + h * 64) * 256;
#pragma unroll
        for (int d = 0; d < 32; d++)
            y1s[d * 256 + tid] = ybase[d * 256 + tid] * scale1;
#pragma unroll
        for (int d = 0; d < 32; d++)
            y2s[d * 260 + tid] = ybase[(32 + d) * 256 + tid] * scale2;
        const float* xbase = g_xs + ((size_t)img * 384 + h * 32) * 1024 + mt * 32;
#pragma unroll
        for (int r = 0; r < 4; r++) {
            int e = tid + 256 * r;
            xrs[e] = xbase[(e >> 5) * 1024 + (e & 31)];
        }
        __syncthreads();

        // GEMM1: attn[n=tid, m0..31] = sum_d y1[d,n]*xr[d,m]
        unsigned long long acc[16];
#pragma unroll
        for (int i = 0; i < 16; i++) acc[i] = pk2(v2[2 * i], v2[2 * i + 1]);
#pragma unroll 4
        for (int d = 0; d < 32; d++) {
            float a = y1s[d * 256 + tid];
            unsigned long long a2 = pk2(a, a);
            const ulonglong2* xr = (const ulonglong2*)&xrs[d * 32];
#pragma unroll
            for (int q = 0; q < 8; q++) {
                ulonglong2 xv = xr[q];
                acc[2 * q]     = ffma2(a2, xv.x, acc[2 * q]);
                acc[2 * q + 1] = ffma2(a2, xv.y, acc[2 * q + 1]);
            }
        }
        // LIF2
#pragma unroll
        for (int q = 0; q < 8; q++) {
            float a0, a1, a2f, a3;
            upk2(acc[2 * q], a0, a1);
            upk2(acc[2 * q + 1], a2f, a3);
            a0 *= 0.5f; a1 *= 0.5f; a2f *= 0.5f; a3 *= 0.5f;
            float4 sv;
            sv.x = (a0  >= 1.0f) ? 1.0f : 0.0f; v2[4 * q + 0] = (a0  >= 1.0f) ? 0.0f : a0;
            sv.y = (a1  >= 1.0f) ? 1.0f : 0.0f; v2[4 * q + 1] = (a1  >= 1.0f) ? 0.0f : a1;
            sv.z = (a2f >= 1.0f) ? 1.0f : 0.0f; v2[4 * q + 2] = (a2f >= 1.0f) ? 0.0f : a2f;
            sv.w = (a3  >= 1.0f) ? 1.0f : 0.0f; v2[4 * q + 3] = (a3  >= 1.0f) ? 0.0f : a3;
            *(float4*)&ss[tid * 36 + 4 * q] = sv;
        }
        __syncthreads();

        // GEMM2: out[dd, m] = sum_n y2[dd,n]*s[n,m]
        unsigned long long acc2[2];
        acc2[0] = pk2(v3[0], v3[1]);
        acc2[1] = pk2(v3[2], v3[3]);
#pragma unroll 4
        for (int nn = 0; nn < 256; nn += 4) {
            float4 bv = *(const float4*)&y2s[dd * 260 + nn];
            ulonglong2 s0 = *(const ulonglong2*)&ss[(nn + 0) * 36 + mg * 4];
            ulonglong2 s1 = *(const ulonglong2*)&ss[(nn + 1) * 36 + mg * 4];
            ulonglong2 s2 = *(const ulonglong2*)&ss[(nn + 2) * 36 + mg * 4];
            ulonglong2 s3 = *(const ulonglong2*)&ss[(nn + 3) * 36 + mg * 4];
            unsigned long long b2;
            b2 = pk2(bv.x, bv.x); acc2[0] = ffma2(b2, s0.x, acc2[0]); acc2[1] = ffma2(b2, s0.y, acc2[1]);
            b2 = pk2(bv.y, bv.y); acc2[0] = ffma2(b2, s1.x, acc2[0]); acc2[1] = ffma2(b2, s1.y, acc2[1]);
            b2 = pk2(bv.z, bv.z); acc2[0] = ffma2(b2, s2.x, acc2[0]); acc2[1] = ffma2(b2, s2.y, acc2[1]);
            b2 = pk2(bv.w, bv.w); acc2[0] = ffma2(b2, s3.x, acc2[0]); acc2[1] = ffma2(b2, s3.y, acc2[1]);
        }
        // LIF3
        float o0, o1, o2, o3;
        upk2(acc2[0], o0, o1); upk2(acc2[1], o2, o3);
        o0 *= 0.5f; o1 *= 0.5f; o2 *= 0.5f; o3 *= 0.5f;
        float4 so;
        so.x = (o0 >= 1.0f) ? 1.0f : 0.0f; v3[0] = (o0 >= 1.0f) ? 0.0f : o0;
        so.y = (o1 >= 1.0f) ? 1.0f : 0.0f; v3[1] = (o1 >= 1.0f) ? 0.0f : o1;
        so.z = (o2 >= 1.0f) ? 1.0f : 0.0f; v3[2] = (o2 >= 1.0f) ? 0.0f : o2;
        so.w = (o3 >= 1.0f) ? 1.0f : 0.0f; v3[3] = (o3 >= 1.0f) ? 0.0f : o3;
        *(float4*)&g_sp3[((size_t)img * 384 + h * 32 + dd) * 1024 + mt * 32 + mg * 4] = so;
        __syncthreads();
    }
}

// ============================================================
// Kernel D: proj GEMM (384x16384, K=384) + BN2 + residual
// 128x128 tile, 8x8/thread, double-buffered.
// grid: 3 ot x 128 nt = 384 blocks, 256 threads
// ============================================================
__global__ void __launch_bounds__(256, 2) proj_kernel(
    const float* __restrict__ Wp, const float* __restrict__ g2,
    const float* __restrict__ b2v, const float* __restrict__ x,
    float* __restrict__ out)
{
    __shared__ __align__(16) float As[2][16][128];
    __shared__ __align__(16) float Bs[2][16][128];
    const int bx = blockIdx.x;
    const int nt = bx & 127;
    const int ot = bx >> 7;
    const int tid = threadIdx.x;
    const int tx = tid & 15, ty = tid >> 4;
    const int obase = ot * 128;
    const int tb = nt >> 3;
    const int hw0 = (nt & 7) * 128;
    const int oA = tid & 127, kh2 = tid >> 7;
    const float bnA = g2[obase + oA] * rsqrtf(1.0f + EPSF);

    unsigned long long acc[8][4];
#pragma unroll
    for (int r = 0; r < 8; r++)
#pragma unroll
        for (int q = 0; q < 4; q++) acc[r][q] = 0ull;

    auto ldA = [&](int kc, int buf) {
#pragma unroll
        for (int v = 0; v < 2; v++) {
            float4 w = *(const float4*)&Wp[(size_t)(obase + oA) * 384 + kc + kh2 * 8 + v * 4];
            As[buf][kh2 * 8 + v * 4 + 0][oA] = w.x * bnA;
            As[buf][kh2 * 8 + v * 4 + 1][oA] = w.y * bnA;
            As[buf][kh2 * 8 + v * 4 + 2][oA] = w.z * bnA;
            As[buf][kh2 * 8 + v * 4 + 3][oA] = w.w * bnA;
        }
    };
    auto ldB = [&](int kc, int buf) {
#pragma unroll
        for (int r = 0; r < 2; r++) {
            int e = tid + 256 * r;
            int k = e >> 5, p4 = e & 31;
            *(float4*)&Bs[buf][k][p4 * 4] =
                *(const float4*)&g_sp3[((size_t)(tb * 384 + kc + k)) * 1024 + hw0 + p4 * 4];
        }
    };

    int buf = 0;
    ldA(0, 0); ldB(0, 0);
    __syncthreads();
    for (int kc = 0; kc < 384; kc += 16) {
        if (kc + 16 < 384) { ldA(kc + 16, buf ^ 1); ldB(kc + 16, buf ^ 1); }
#pragma unroll
        for (int k = 0; k < 16; k++) {
            float4 a0 = *(const float4*)&As[buf][k][ty * 8];
            float4 a1 = *(const float4*)&As[buf][k][ty * 8 + 4];
            ulonglong2 b0 = *(const ulonglong2*)&Bs[buf][k][tx * 8];
            ulonglong2 b1 = *(const ulonglong2*)&Bs[buf][k][tx * 8 + 4];
            float av[8] = {a0.x, a0.y, a0.z, a0.w, a1.x, a1.y, a1.z, a1.w};
#pragma unroll
            for (int r = 0; r < 8; r++) {
                unsigned long long ar = pk2(av[r], av[r]);
                acc[r][0] = ffma2(ar, b0.x, acc[r][0]);
                acc[r][1] = ffma2(ar, b0.y, acc[r][1]);
                acc[r][2] = ffma2(ar, b1.x, acc[r][2]);
                acc[r][3] = ffma2(ar, b1.y, acc[r][3]);
            }
        }
        __syncthreads();
        buf ^= 1;
    }

#pragma unroll
    for (int r = 0; r < 8; r++) {
        int o = obase + ty * 8 + r;
        size_t idx = ((size_t)tb * 384 + o) * 1024 + hw0 + tx * 8;
        float4 xv0 = *(const float4*)&x[idx];
        float4 xv1 = *(const float4*)&x[idx + 4];
        float bt = b2v[o];
        float v0, v1, v2, v3, v4, v5, v6, v7;
        upk2(acc[r][0], v0, v1); upk2(acc[r][1], v2, v3);
        upk2(acc[r][2], v4, v5); upk2(acc[r][3], v6, v7);
        *(float4*)&out[idx]     = make_float4(v0 + bt + xv0.x, v1 + bt + xv0.y,
                                              v2 + bt + xv0.z, v3 + bt + xv0.w);
        *(float4*)&out[idx + 4] = make_float4(v4 + bt + xv1.x, v5 + bt + xv1.y,
                                              v6 + bt + xv1.z, v7 + bt + xv1.w);
    }
}

// ============================================================
extern "C" void kernel_launch(void* const* d_in, const int* in_sizes, int n_in,
                              void* d_out, int out_size) {
    const float* x   = (const float*)d_in[0];
    const float* Wc  = (const float*)d_in[1];
    const float* g1  = (const float*)d_in[2];
    const float* b1  = (const float*)d_in[3];
    const float* Wp  = (const float*)d_in[4];
    const float* g2  = (const float*)d_in[5];
    const float* b2  = (const float*)d_in[6];
    const float* frx = (const float*)d_in[7];
    const float* fra = (const float*)d_in[8];
    float* out = (float*)d_out;

    const int smem_attn = 26752 * 4;  // 107,008 B
    cudaFuncSetAttribute(attn_fused_kernel,
                         cudaFuncAttributeMaxDynamicSharedMemorySize, smem_attn);

    lif1_kernel<<<6144, 256>>>(x);
    conv_partial_kernel<<<576, 256>>>(Wc);
    reduce_bn_kernel<<<3072, 256>>>(g1, b1);
    attn_fused_kernel<<<1536, 256, smem_attn>>>(frx, fra);
    proj_kernel<<<384, 256>>>(Wp, g2, b2, x, out);
}

// round 3
// speedup vs baseline: 1.3935x; 1.2864x over previous
#include <cuda_runtime.h>

#define EPSF 1e-5f

// Scratch (device globals; no allocations allowed)
static __device__ float g_xs[6291456];        // LIF1 spikes (T,B,C,H,W)
static __device__ float g_y [3145728];        // conv+BN output (16,768,16,16)
static __device__ float g_yp[3][3145728];     // conv K-split partials
static __device__ float g_sp3[6291456];       // LIF3 spikes (T,B,C,H,W)

// ---- packed fp32x2 helpers (Blackwell FFMA2 via PTX) ----
__device__ __forceinline__ unsigned long long pk2(float lo, float hi) {
    unsigned long long r;
    asm("mov.b64 %0, {%1,%2};" : "=l"(r) : "f"(lo), "f"(hi));
    return r;
}
__device__ __forceinline__ void upk2(unsigned long long v, float& lo, float& hi) {
    asm("mov.b64 {%0,%1}, %2;" : "=f"(lo), "=f"(hi) : "l"(v));
}
__device__ __forceinline__ unsigned long long ffma2(unsigned long long a,
                                                    unsigned long long b,
                                                    unsigned long long c) {
    unsigned long long d;
    asm("fma.rn.f32x2 %0, %1, %2, %3;" : "=l"(d) : "l"(a), "l"(b), "l"(c));
    return d;
}

// ============================================================
// Kernel A: LIF over T on x -> spikes g_xs
// ============================================================
__global__ void __launch_bounds__(256) lif1_kernel(const float* __restrict__ x) {
    const int S = 4 * 384 * 1024;
    int i = blockIdx.x * blockDim.x + threadIdx.x;
    if (i >= S) return;
    float v = 0.0f;
#pragma unroll
    for (int t = 0; t < 4; t++) {
        v = 0.5f * (v + x[(size_t)t * S + i]);
        bool s = (v >= 1.0f);
        g_xs[(size_t)t * S + i] = s ? 1.0f : 0.0f;
        v = s ? 0.0f : v;
    }
}

// ============================================================
// Kernel B: conv-as-GEMM partials. 128x128 tile, 8x8/thread,
// double-buffered smem, K split 3 ways (512 each).
// ============================================================
__global__ void __launch_bounds__(256, 2) conv_partial_kernel(
    const float* __restrict__ Wc)
{
    __shared__ __align__(16) float As[2][16][128];
    __shared__ __align__(16) float Bs[2][16][128];
    const int bx = blockIdx.x;
    const int ks = bx / 192;
    const int rem = bx % 192;
    const int img = rem / 12;
    const int ot = (rem % 12) >> 1;
    const int pt = rem & 1;
    const int kbase = ks * 512;
    const int tid = threadIdx.x;
    const int tx = tid & 15, ty = tid >> 4;
    const int obase = ot * 128, pbase = pt * 128;
    const int oA = tid & 127, kh2 = tid >> 7;
    const float* xsb = g_xs + (size_t)img * 393216;

    unsigned long long acc[8][4];
#pragma unroll
    for (int r = 0; r < 8; r++)
#pragma unroll
        for (int q = 0; q < 4; q++) acc[r][q] = 0ull;

    auto ldA = [&](int kc, int buf) {
#pragma unroll
        for (int v = 0; v < 2; v++) {
            float4 w = *(const float4*)&Wc[(size_t)(obase + oA) * 1536 + kc + kh2 * 8 + v * 4];
            As[buf][kh2 * 8 + v * 4 + 0][oA] = w.x;
            As[buf][kh2 * 8 + v * 4 + 1][oA] = w.y;
            As[buf][kh2 * 8 + v * 4 + 2][oA] = w.z;
            As[buf][kh2 * 8 + v * 4 + 3][oA] = w.w;
        }
    };
    auto ldB = [&](int kc, int buf) {
#pragma unroll
        for (int r = 0; r < 8; r++) {
            int e = tid + 256 * r;
            int k = e >> 7, p = e & 127;
            int kk = kc + k;
            int c = kk >> 2, kh = (kk >> 1) & 1, kw = kk & 1;
            int pp = pbase + p;
            int ii = pp >> 4, jj = pp & 15;
            Bs[buf][k][p] = xsb[(c * 32 + 2 * ii + kh) * 32 + 2 * jj + kw];
        }
    };

    int buf = 0;
    ldA(kbase, 0); ldB(kbase, 0);
    __syncthreads();
    for (int kc = 0; kc < 512; kc += 16) {
        if (kc + 16 < 512) { ldA(kbase + kc + 16, buf ^ 1); ldB(kbase + kc + 16, buf ^ 1); }
#pragma unroll
        for (int k = 0; k < 16; k++) {
            float4 a0 = *(const float4*)&As[buf][k][ty * 8];
            float4 a1 = *(const float4*)&As[buf][k][ty * 8 + 4];
            ulonglong2 b0 = *(const ulonglong2*)&Bs[buf][k][tx * 8];
            ulonglong2 b1 = *(const ulonglong2*)&Bs[buf][k][tx * 8 + 4];
            float av[8] = {a0.x, a0.y, a0.z, a0.w, a1.x, a1.y, a1.z, a1.w};
#pragma unroll
            for (int r = 0; r < 8; r++) {
                unsigned long long ar = pk2(av[r], av[r]);
                acc[r][0] = ffma2(ar, b0.x, acc[r][0]);
                acc[r][1] = ffma2(ar, b0.y, acc[r][1]);
                acc[r][2] = ffma2(ar, b1.x, acc[r][2]);
                acc[r][3] = ffma2(ar, b1.y, acc[r][3]);
            }
        }
        __syncthreads();
        buf ^= 1;
    }

    float* yo = g_yp[ks] + ((size_t)img * 768 + obase) * 256 + pbase + tx * 8;
#pragma unroll
    for (int r = 0; r < 8; r++) {
        int o = ty * 8 + r;
        *(ulonglong2*)(yo + (size_t)o * 256)     = make_ulonglong2(acc[r][0], acc[r][1]);
        *(ulonglong2*)(yo + (size_t)o * 256 + 4) = make_ulonglong2(acc[r][2], acc[r][3]);
    }
}

// ============================================================
// Kernel B2: reduce 3 K-split partials + BN1 -> g_y
// ============================================================
__global__ void __launch_bounds__(256) reduce_bn_kernel(
    const float* __restrict__ g1, const float* __restrict__ b1)
{
    int i4 = blockIdx.x * 256 + threadIdx.x;
    const float4* p0 = (const float4*)g_yp[0];
    const float4* p1 = (const float4*)g_yp[1];
    const float4* p2 = (const float4*)g_yp[2];
    float4 a = p0[i4], b = p1[i4], c = p2[i4];
    int o = (i4 >> 6) % 768;
    const float rs = rsqrtf(1.0f + EPSF);
    float bn = g1[o] * rs, bt = b1[o];
    ((float4*)g_y)[i4] = make_float4(
        (a.x + b.x + c.x) * bn + bt,
        (a.y + b.y + c.y) * bn + bt,
        (a.z + b.z + c.z) * bn + bt,
        (a.w + b.w + c.w) * bn + bt);
}

// ============================================================
// Kernel C: fused attn GEMM -> LIF2 -> out GEMM(ksplit8) -> LIF3
// grid: b(4) x h(12) x mtile(32) = 1536 blocks, 256 threads
// smem layout (floats):
//   y1s [32][256]   @ 0      (8192)   } overlaid by sp[8][32][36]
//   xrs [32][32]    @ 8192   (1024)   } (9216) during GEMM2 epi
//   y2s [32][260]   @ 9216   (8320)
//   ss  [256][36]   @ 17536  (9216)
// ============================================================
__global__ void __launch_bounds__(256, 2) attn_fused_kernel(
    const float* __restrict__ frx, const float* __restrict__ fra)
{
    extern __shared__ __align__(16) float sm[];
    float* y1s = sm;
    float* xrs = sm + 8192;
    float* y2s = sm + 9216;
    float* ss  = sm + 17536;
    float* sp  = sm;  // overlay

    const int bx = blockIdx.x;
    const int mt = bx & 31;
    const int h  = (bx >> 5) % 12;
    const int b  = bx / 384;
    const int tid = threadIdx.x;

    // GEMM1 mapping: 4n x 8m per thread
    const int ng = tid >> 2;       // 0..63 -> n0 = ng*4
    const int mg = tid & 3;        // 0..3  -> m0 = mg*8
    const int n0 = ng * 4, m0 = mg * 8;
    // GEMM2 mapping: warp kg handles n chunk [kg*32, kg*32+32); 4d x 8m per lane
    const int kg = tid >> 5;
    const int lane = tid & 31;
    const int dg = lane >> 2;      // d rows: dg, dg+8, dg+16, dg+24
    const int mq = lane & 3;       // m0g = mq*8
    // reduce/output mapping: 1d x 4m per thread
    const int rd = tid >> 3;       // 0..31
    const int rm = (tid & 7) * 4;  // 0..28

    const float scale1 = rsqrtf(frx[h] * 32.0f);
    const float scale2 = rsqrtf(fra[h] * 256.0f);

    float v2[4][8];                // LIF2 state (4n x 8m tile)
    float v3[4];                   // LIF3 state (1d x 4m tile)
#pragma unroll
    for (int i = 0; i < 4; i++)
#pragma unroll
        for (int j = 0; j < 8; j++) v2[i][j] = 0.0f;
#pragma unroll
    for (int i = 0; i < 4; i++) v3[i] = 0.0f;

    for (int t = 0; t < 4; t++) {
        const int img = t * 4 + b;
        const float* ybase = g_y + ((size_t)img * 768 + h * 64) * 256;
        // vectorized loads: y1s (scaled), y2s (scaled), xrs
#pragma unroll
        for (int r = 0; r < 8; r++) {
            int e = tid + 256 * r;         // f4 index over 2048
            int d = e >> 6, c4 = (e & 63) * 4;
            float4 w = *(const float4*)&ybase[d * 256 + c4];
            *(float4*)&y1s[d * 256 + c4] = make_float4(
                w.x * scale1, w.y * scale1, w.z * scale1, w.w * scale1);
        }
#pragma unroll
        for (int r = 0; r < 8; r++) {
            int e = tid + 256 * r;
            int d = e >> 6, c4 = (e & 63) * 4;
            float4 w = *(const float4*)&ybase[(32 + d) * 256 + c4];
            *(float4*)&y2s[d * 260 + c4] = make_float4(
                w.x * scale2, w.y * scale2, w.z * scale2, w.w * scale2);
        }
        {
            const float* xbase = g_xs + ((size_t)img * 384 + h * 32) * 1024 + mt * 32;
            int d = tid >> 3, c4 = (tid & 7) * 4;
            *(float4*)&xrs[d * 32 + c4] = *(const float4*)&xbase[d * 1024 + c4];
        }
        __syncthreads();

        // ---- GEMM1: attn[n0..+3][m0..+7] = sum_d y1[d][n]*xr[d][m], seed v2 ----
        unsigned long long acc[4][4];
#pragma unroll
        for (int i = 0; i < 4; i++)
#pragma unroll
            for (int q = 0; q < 4; q++) acc[i][q] = pk2(v2[i][2 * q], v2[i][2 * q + 1]);
#pragma unroll 8
        for (int d = 0; d < 32; d++) {
            float4 a4 = *(const float4*)&y1s[d * 256 + n0];
            ulonglong2 x0 = *(const ulonglong2*)&xrs[d * 32 + m0];
            ulonglong2 x1 = *(const ulonglong2*)&xrs[d * 32 + m0 + 4];
            float av[4] = {a4.x, a4.y, a4.z, a4.w};
#pragma unroll
            for (int i = 0; i < 4; i++) {
                unsigned long long ar = pk2(av[i], av[i]);
                acc[i][0] = ffma2(ar, x0.x, acc[i][0]);
                acc[i][1] = ffma2(ar, x0.y, acc[i][1]);
                acc[i][2] = ffma2(ar, x1.x, acc[i][2]);
                acc[i][3] = ffma2(ar, x1.y, acc[i][3]);
            }
        }
        // ---- LIF2 ----
#pragma unroll
        for (int i = 0; i < 4; i++) {
            float s[8];
#pragma unroll
            for (int q = 0; q < 4; q++) {
                float lo, hi;
                upk2(acc[i][q], lo, hi);
                lo *= 0.5f; hi *= 0.5f;
                s[2 * q]     = (lo >= 1.0f) ? 1.0f : 0.0f;
                s[2 * q + 1] = (hi >= 1.0f) ? 1.0f : 0.0f;
                v2[i][2 * q]     = (lo >= 1.0f) ? 0.0f : lo;
                v2[i][2 * q + 1] = (hi >= 1.0f) ? 0.0f : hi;
            }
            *(float4*)&ss[(n0 + i) * 36 + m0]     = make_float4(s[0], s[1], s[2], s[3]);
            *(float4*)&ss[(n0 + i) * 36 + m0 + 4] = make_float4(s[4], s[5], s[6], s[7]);
        }
        __syncthreads();

        // ---- GEMM2 (ksplit 8): partial[d][m] over n in [kg*32, kg*32+32) ----
        unsigned long long acc2[4][4];
#pragma unroll
        for (int i = 0; i < 4; i++)
#pragma unroll
            for (int q = 0; q < 4; q++) acc2[i][q] = 0ull;
#pragma unroll
        for (int nn = 0; nn < 32; nn += 4) {
            int n = kg * 32 + nn;
            float4 b0 = *(const float4*)&y2s[(dg +  0) * 260 + n];
            float4 b1 = *(const float4*)&y2s[(dg +  8) * 260 + n];
            float4 b2 = *(const float4*)&y2s[(dg + 16) * 260 + n];
            float4 b3 = *(const float4*)&y2s[(dg + 24) * 260 + n];
            float bv[4][4] = {{b0.x, b0.y, b0.z, b0.w}, {b1.x, b1.y, b1.z, b1.w},
                              {b2.x, b2.y, b2.z, b2.w}, {b3.x, b3.y, b3.z, b3.w}};
#pragma unroll
            for (int j = 0; j < 4; j++) {
                ulonglong2 s0 = *(const ulonglong2*)&ss[(n + j) * 36 + mq * 8];
                ulonglong2 s1 = *(const ulonglong2*)&ss[(n + j) * 36 + mq * 8 + 4];
#pragma unroll
                for (int i = 0; i < 4; i++) {
                    unsigned long long ar = pk2(bv[i][j], bv[i][j]);
                    acc2[i][0] = ffma2(ar, s0.x, acc2[i][0]);
                    acc2[i][1] = ffma2(ar, s0.y, acc2[i][1]);
                    acc2[i][2] = ffma2(ar, s1.x, acc2[i][2]);
                    acc2[i][3] = ffma2(ar, s1.y, acc2[i][3]);
                }
            }
        }
        __syncthreads();  // y1s/xrs fully consumed; safe to overlay sp
#pragma unroll
        for (int i = 0; i < 4; i++) {
            float* dst = &sp[kg * 1152 + (dg + 8 * i) * 36 + mq * 8];
            *(ulonglong2*)dst       = make_ulonglong2(acc2[i][0], acc2[i][1]);
            *(ulonglong2*)(dst + 4) = make_ulonglong2(acc2[i][2], acc2[i][3]);
        }
        __syncthreads();

        // ---- reduce 8 partials + LIF3 + store ----
        float4 sum = make_float4(v3[0], v3[1], v3[2], v3[3]);
#pragma unroll
        for (int k = 0; k < 8; k++) {
            float4 p = *(const float4*)&sp[k * 1152 + rd * 36 + rm];
            sum.x += p.x; sum.y += p.y; sum.z += p.z; sum.w += p.w;
        }
        sum.x *= 0.5f; sum.y *= 0.5f; sum.z *= 0.5f; sum.w *= 0.5f;
        float4 so;
        so.x = (sum.x >= 1.0f) ? 1.0f : 0.0f; v3[0] = (sum.x >= 1.0f) ? 0.0f : sum.x;
        so.y = (sum.y >= 1.0f) ? 1.0f : 0.0f; v3[1] = (sum.y >= 1.0f) ? 0.0f : sum.y;
        so.z = (sum.z >= 1.0f) ? 1.0f : 0.0f; v3[2] = (sum.z >= 1.0f) ? 0.0f : sum.z;
        so.w = (sum.w >= 1.0f) ? 1.0f : 0.0f; v3[3] = (sum.w >= 1.0f) ? 0.0f : sum.w;
        *(float4*)&g_sp3[((size_t)img * 384 + h * 32 + rd) * 1024 + mt * 32 + rm] = so;
        __syncthreads();  // sp region reused as y1s next t
    }
}

// ============================================================
// Kernel D: proj GEMM (384x16384, K=384) + BN2 + residual
// ============================================================
__global__ void __launch_bounds__(256, 2) proj_kernel(
    const float* __restrict__ Wp, const float* __restrict__ g2,
    const float* __restrict__ b2v, const float* __restrict__ x,
    float* __restrict__ out)
{
    __shared__ __align__(16) float As[2][16][128];
    __shared__ __align__(16) float Bs[2][16][128];
    const int bx = blockIdx.x;
    const int nt = bx & 127;
    const int ot = bx >> 7;
    const int tid = threadIdx.x;
    const int tx = tid & 15, ty = tid >> 4;
    const int obase = ot * 128;
    const int tb = nt >> 3;
    const int hw0 = (nt & 7) * 128;
    const int oA = tid & 127, kh2 = tid >> 7;
    const float bnA = g2[obase + oA] * rsqrtf(1.0f + EPSF);

    unsigned long long acc[8][4];
#pragma unroll
    for (int r = 0; r < 8; r++)
#pragma unroll
        for (int q = 0; q < 4; q++) acc[r][q] = 0ull;

    auto ldA = [&](int kc, int buf) {
#pragma unroll
        for (int v = 0; v < 2; v++) {
            float4 w = *(const float4*)&Wp[(size_t)(obase + oA) * 384 + kc + kh2 * 8 + v * 4];
            As[buf][kh2 * 8 + v * 4 + 0][oA] = w.x * bnA;
            As[buf][kh2 * 8 + v * 4 + 1][oA] = w.y * bnA;
            As[buf][kh2 * 8 + v * 4 + 2][oA] = w.z * bnA;
            As[buf][kh2 * 8 + v * 4 + 3][oA] = w.w * bnA;
        }
    };
    auto ldB = [&](int kc, int buf) {
#pragma unroll
        for (int r = 0; r < 2; r++) {
            int e = tid + 256 * r;
            int k = e >> 5, p4 = e & 31;
            *(float4*)&Bs[buf][k][p4 * 4] =
                *(const float4*)&g_sp3[((size_t)(tb * 384 + kc + k)) * 1024 + hw0 + p4 * 4];
        }
    };

    int buf = 0;
    ldA(0, 0); ldB(0, 0);
    __syncthreads();
    for (int kc = 0; kc < 384; kc += 16) {
        if (kc + 16 < 384) { ldA(kc + 16, buf ^ 1); ldB(kc + 16, buf ^ 1); }
#pragma unroll
        for (int k = 0; k < 16; k++) {
            float4 a0 = *(const float4*)&As[buf][k][ty * 8];
            float4 a1 = *(const float4*)&As[buf][k][ty * 8 + 4];
            ulonglong2 b0 = *(const ulonglong2*)&Bs[buf][k][tx * 8];
            ulonglong2 b1 = *(const ulonglong2*)&Bs[buf][k][tx * 8 + 4];
            float av[8] = {a0.x, a0.y, a0.z, a0.w, a1.x, a1.y, a1.z, a1.w};
#pragma unroll
            for (int r = 0; r < 8; r++) {
                unsigned long long ar = pk2(av[r], av[r]);
                acc[r][0] = ffma2(ar, b0.x, acc[r][0]);
                acc[r][1] = ffma2(ar, b0.y, acc[r][1]);
                acc[r][2] = ffma2(ar, b1.x, acc[r][2]);
                acc[r][3] = ffma2(ar, b1.y, acc[r][3]);
            }
        }
        __syncthreads();
        buf ^= 1;
    }

#pragma unroll
    for (int r = 0; r < 8; r++) {
        int o = obase + ty * 8 + r;
        size_t idx = ((size_t)tb * 384 + o) * 1024 + hw0 + tx * 8;
        float4 xv0 = *(const float4*)&x[idx];
        float4 xv1 = *(const float4*)&x[idx + 4];
        float bt = b2v[o];
        float v0, v1, v2, v3, v4, v5, v6, v7;
        upk2(acc[r][0], v0, v1); upk2(acc[r][1], v2, v3);
        upk2(acc[r][2], v4, v5); upk2(acc[r][3], v6, v7);
        *(float4*)&out[idx]     = make_float4(v0 + bt + xv0.x, v1 + bt + xv0.y,
                                              v2 + bt + xv0.z, v3 + bt + xv0.w);
        *(float4*)&out[idx + 4] = make_float4(v4 + bt + xv1.x, v5 + bt + xv1.y,
                                              v6 + bt + xv1.z, v7 + bt + xv1.w);
    }
}

// ============================================================
extern "C" void kernel_launch(void* const* d_in, const int* in_sizes, int n_in,
                              void* d_out, int out_size) {
    const float* x   = (const float*)d_in[0];
    const float* Wc  = (const float*)d_in[1];
    const float* g1  = (const float*)d_in[2];
    const float* b1  = (const float*)d_in[3];
    const float* Wp  = (const float*)d_in[4];
    const float* g2  = (const float*)d_in[5];
    const float* b2  = (const float*)d_in[6];
    const float* frx = (const float*)d_in[7];
    const float* fra = (const float*)d_in[8];
    float* out = (float*)d_out;

    const int smem_attn = 26752 * 4;  // 107,008 B
    cudaFuncSetAttribute(attn_fused_kernel,
                         cudaFuncAttributeMaxDynamicSharedMemorySize, smem_attn);

    lif1_kernel<<<6144, 256>>>(x);
    conv_partial_kernel<<<576, 256>>>(Wc);
    reduce_bn_kernel<<<3072, 256>>>(g1, b1);
    attn_fused_kernel<<<1536, 256, smem_attn>>>(frx, fra);
    proj_kernel<<<384, 256>>>(Wp, g2, b2, x, out);
}

// round 4
// speedup vs baseline: 1.3968x; 1.0024x over previous
#include <cuda_runtime.h>

#define EPSF 1e-5f

// Scratch (device globals; no allocations allowed)
static __device__ float g_xs[6291456];        // LIF1 spikes (T,B,C,H,W)
static __device__ float g_y [3145728];        // conv+BN output (16,768,16,16)
static __device__ float g_yp[3][3145728];     // conv K-split partials
static __device__ float g_sp3[6291456];       // LIF3 spikes (T,B,C,H,W)

// ---- packed fp32x2 helpers (Blackwell FFMA2 via PTX) ----
__device__ __forceinline__ unsigned long long pk2(float lo, float hi) {
    unsigned long long r;
    asm("mov.b64 %0, {%1,%2};" : "=l"(r) : "f"(lo), "f"(hi));
    return r;
}
__device__ __forceinline__ void upk2(unsigned long long v, float& lo, float& hi) {
    asm("mov.b64 {%0,%1}, %2;" : "=f"(lo), "=f"(hi) : "l"(v));
}
__device__ __forceinline__ unsigned long long ffma2(unsigned long long a,
                                                    unsigned long long b,
                                                    unsigned long long c) {
    unsigned long long d;
    asm("fma.rn.f32x2 %0, %1, %2, %3;" : "=l"(d) : "l"(a), "l"(b), "l"(c));
    return d;
}

// ============================================================
// Kernel A: LIF over T on x -> spikes g_xs
// ============================================================
__global__ void __launch_bounds__(256) lif1_kernel(const float* __restrict__ x) {
    const int S = 4 * 384 * 1024;
    int i = blockIdx.x * blockDim.x + threadIdx.x;
    if (i >= S) return;
    float v = 0.0f;
#pragma unroll
    for (int t = 0; t < 4; t++) {
        v = 0.5f * (v + x[(size_t)t * S + i]);
        bool s = (v >= 1.0f);
        g_xs[(size_t)t * S + i] = s ? 1.0f : 0.0f;
        v = s ? 0.0f : v;
    }
}

// ============================================================
// Kernel B: conv-as-GEMM partials. 128x128 tile, 8x8/thread,
// double-buffered smem, K split 3 ways (512 each).
// ============================================================
__global__ void __launch_bounds__(256, 2) conv_partial_kernel(
    const float* __restrict__ Wc)
{
    __shared__ __align__(16) float As[2][16][128];
    __shared__ __align__(16) float Bs[2][16][128];
    const int bx = blockIdx.x;
    const int ks = bx / 192;
    const int rem = bx % 192;
    const int img = rem / 12;
    const int ot = (rem % 12) >> 1;
    const int pt = rem & 1;
    const int kbase = ks * 512;
    const int tid = threadIdx.x;
    const int tx = tid & 15, ty = tid >> 4;
    const int obase = ot * 128, pbase = pt * 128;
    const int oA = tid & 127, kh2 = tid >> 7;
    const float* xsb = g_xs + (size_t)img * 393216;

    unsigned long long acc[8][4];
#pragma unroll
    for (int r = 0; r < 8; r++)
#pragma unroll
        for (int q = 0; q < 4; q++) acc[r][q] = 0ull;

    auto ldA = [&](int kc, int buf) {
#pragma unroll
        for (int v = 0; v < 2; v++) {
            float4 w = *(const float4*)&Wc[(size_t)(obase + oA) * 1536 + kc + kh2 * 8 + v * 4];
            As[buf][kh2 * 8 + v * 4 + 0][oA] = w.x;
            As[buf][kh2 * 8 + v * 4 + 1][oA] = w.y;
            As[buf][kh2 * 8 + v * 4 + 2][oA] = w.z;
            As[buf][kh2 * 8 + v * 4 + 3][oA] = w.w;
        }
    };
    auto ldB = [&](int kc, int buf) {
#pragma unroll
        for (int r = 0; r < 8; r++) {
            int e = tid + 256 * r;
            int k = e >> 7, p = e & 127;
            int kk = kc + k;
            int c = kk >> 2, kh = (kk >> 1) & 1, kw = kk & 1;
            int pp = pbase + p;
            int ii = pp >> 4, jj = pp & 15;
            Bs[buf][k][p] = xsb[(c * 32 + 2 * ii + kh) * 32 + 2 * jj + kw];
        }
    };

    int buf = 0;
    ldA(kbase, 0); ldB(kbase, 0);
    __syncthreads();
    for (int kc = 0; kc < 512; kc += 16) {
        if (kc + 16 < 512) { ldA(kbase + kc + 16, buf ^ 1); ldB(kbase + kc + 16, buf ^ 1); }
#pragma unroll
        for (int k = 0; k < 16; k++) {
            float4 a0 = *(const float4*)&As[buf][k][ty * 8];
            float4 a1 = *(const float4*)&As[buf][k][ty * 8 + 4];
            ulonglong2 b0 = *(const ulonglong2*)&Bs[buf][k][tx * 8];
            ulonglong2 b1 = *(const ulonglong2*)&Bs[buf][k][tx * 8 + 4];
            float av[8] = {a0.x, a0.y, a0.z, a0.w, a1.x, a1.y, a1.z, a1.w};
#pragma unroll
            for (int r = 0; r < 8; r++) {
                unsigned long long ar = pk2(av[r], av[r]);
                acc[r][0] = ffma2(ar, b0.x, acc[r][0]);
                acc[r][1] = ffma2(ar, b0.y, acc[r][1]);
                acc[r][2] = ffma2(ar, b1.x, acc[r][2]);
                acc[r][3] = ffma2(ar, b1.y, acc[r][3]);
            }
        }
        __syncthreads();
        buf ^= 1;
    }

    float* yo = g_yp[ks] + ((size_t)img * 768 + obase) * 256 + pbase + tx * 8;
#pragma unroll
    for (int r = 0; r < 8; r++) {
        int o = ty * 8 + r;
        *(ulonglong2*)(yo + (size_t)o * 256)     = make_ulonglong2(acc[r][0], acc[r][1]);
        *(ulonglong2*)(yo + (size_t)o * 256 + 4) = make_ulonglong2(acc[r][2], acc[r][3]);
    }
}

// ============================================================
// Kernel B2: reduce 3 K-split partials + BN1 -> g_y
// ============================================================
__global__ void __launch_bounds__(256) reduce_bn_kernel(
    const float* __restrict__ g1, const float* __restrict__ b1)
{
    int i4 = blockIdx.x * 256 + threadIdx.x;
    const float4* p0 = (const float4*)g_yp[0];
    const float4* p1 = (const float4*)g_yp[1];
    const float4* p2 = (const float4*)g_yp[2];
    float4 a = p0[i4], b = p1[i4], c = p2[i4];
    int o = (i4 >> 6) % 768;
    const float rs = rsqrtf(1.0f + EPSF);
    float bn = g1[o] * rs, bt = b1[o];
    ((float4*)g_y)[i4] = make_float4(
        (a.x + b.x + c.x) * bn + bt,
        (a.y + b.y + c.y) * bn + bt,
        (a.z + b.z + c.z) * bn + bt,
        (a.w + b.w + c.w) * bn + bt);
}

// ============================================================
// Kernel C: fused attn GEMM -> LIF2 -> out GEMM(ksplit8) -> LIF3
// grid: b(4) x h(12) x mtile(32) = 1536 blocks, 256 threads
// smem layout (floats):
//   y1s [32][256]   @ 0      (8192)   } overlaid by sp[8][32][36]
//   xrs [32][32]    @ 8192   (1024)   } (9216) during GEMM2 epi
//   y2s [32][260]   @ 9216   (8320)
//   ss  [256][36]   @ 17536  (9216)
// ============================================================
__global__ void __launch_bounds__(256, 2) attn_fused_kernel(
    const float* __restrict__ frx, const float* __restrict__ fra)
{
    extern __shared__ __align__(16) float sm[];
    float* y1s = sm;
    float* xrs = sm + 8192;
    float* y2s = sm + 9216;
    float* ss  = sm + 17536;
    float* sp  = sm;  // overlay

    const int bx = blockIdx.x;
    const int mt = bx & 31;
    const int h  = (bx >> 5) % 12;
    const int b  = bx / 384;
    const int tid = threadIdx.x;

    // GEMM1 mapping: 4n x 8m per thread
    const int ng = tid >> 2;       // 0..63 -> n0 = ng*4
    const int mg = tid & 3;        // 0..3  -> m0 = mg*8
    const int n0 = ng * 4, m0 = mg * 8;
    // GEMM2 mapping: warp kg handles n chunk [kg*32, kg*32+32); 4d x 8m per lane
    const int kg = tid >> 5;
    const int lane = tid & 31;
    const int dg = lane >> 2;      // d rows: dg, dg+8, dg+16, dg+24
    const int mq = lane & 3;       // m0g = mq*8
    // reduce/output mapping: 1d x 4m per thread
    const int rd = tid >> 3;       // 0..31
    const int rm = (tid & 7) * 4;  // 0..28

    const float scale1 = rsqrtf(frx[h] * 32.0f);
    const float scale2 = rsqrtf(fra[h] * 256.0f);

    float v2[4][8];                // LIF2 state (4n x 8m tile)
    float v3[4];                   // LIF3 state (1d x 4m tile)
#pragma unroll
    for (int i = 0; i < 4; i++)
#pragma unroll
        for (int j = 0; j < 8; j++) v2[i][j] = 0.0f;
#pragma unroll
    for (int i = 0; i < 4; i++) v3[i] = 0.0f;

    for (int t = 0; t < 4; t++) {
        const int img = t * 4 + b;
        const float* ybase = g_y + ((size_t)img * 768 + h * 64) * 256;
        // vectorized loads: y1s (scaled), y2s (scaled), xrs
#pragma unroll
        for (int r = 0; r < 8; r++) {
            int e = tid + 256 * r;         // f4 index over 2048
            int d = e >> 6, c4 = (e & 63) * 4;
            float4 w = *(const float4*)&ybase[d * 256 + c4];
            *(float4*)&y1s[d * 256 + c4] = make_float4(
                w.x * scale1, w.y * scale1, w.z * scale1, w.w * scale1);
        }
#pragma unroll
        for (int r = 0; r < 8; r++) {
            int e = tid + 256 * r;
            int d = e >> 6, c4 = (e & 63) * 4;
            float4 w = *(const float4*)&ybase[(32 + d) * 256 + c4];
            *(float4*)&y2s[d * 260 + c4] = make_float4(
                w.x * scale2, w.y * scale2, w.z * scale2, w.w * scale2);
        }
        {
            const float* xbase = g_xs + ((size_t)img * 384 + h * 32) * 1024 + mt * 32;
            int d = tid >> 3, c4 = (tid & 7) * 4;
            *(float4*)&xrs[d * 32 + c4] = *(const float4*)&xbase[d * 1024 + c4];
        }
        __syncthreads();

        // ---- GEMM1: attn[n0..+3][m0..+7] = sum_d y1[d][n]*xr[d][m], seed v2 ----
        unsigned long long acc[4][4];
#pragma unroll
        for (int i = 0; i < 4; i++)
#pragma unroll
            for (int q = 0; q < 4; q++) acc[i][q] = pk2(v2[i][2 * q], v2[i][2 * q + 1]);
#pragma unroll 8
        for (int d = 0; d < 32; d++) {
            float4 a4 = *(const float4*)&y1s[d * 256 + n0];
            ulonglong2 x0 = *(const ulonglong2*)&xrs[d * 32 + m0];
            ulonglong2 x1 = *(const ulonglong2*)&xrs[d * 32 + m0 + 4];
            float av[4] = {a4.x, a4.y, a4.z, a4.w};
#pragma unroll
            for (int i = 0; i < 4; i++) {
                unsigned long long ar = pk2(av[i], av[i]);
                acc[i][0] = ffma2(ar, x0.x, acc[i][0]);
                acc[i][1] = ffma2(ar, x0.y, acc[i][1]);
                acc[i][2] = ffma2(ar, x1.x, acc[i][2]);
                acc[i][3] = ffma2(ar, x1.y, acc[i][3]);
            }
        }
        // ---- LIF2 ----
#pragma unroll
        for (int i = 0; i < 4; i++) {
            float s[8];
#pragma unroll
            for (int q = 0; q < 4; q++) {
                float lo, hi;
                upk2(acc[i][q], lo, hi);
                lo *= 0.5f; hi *= 0.5f;
                s[2 * q]     = (lo >= 1.0f) ? 1.0f : 0.0f;
                s[2 * q + 1] = (hi >= 1.0f) ? 1.0f : 0.0f;
                v2[i][2 * q]     = (lo >= 1.0f) ? 0.0f : lo;
                v2[i][2 * q + 1] = (hi >= 1.0f) ? 0.0f : hi;
            }
            *(float4*)&ss[(n0 + i) * 36 + m0]     = make_float4(s[0], s[1], s[2], s[3]);
            *(float4*)&ss[(n0 + i) * 36 + m0 + 4] = make_float4(s[4], s[5], s[6], s[7]);
        }
        __syncthreads();

        // ---- GEMM2 (ksplit 8): partial[d][m] over n in [kg*32, kg*32+32) ----
        unsigned long long acc2[4][4];
#pragma unroll
        for (int i = 0; i < 4; i++)
#pragma unroll
            for (int q = 0; q < 4; q++) acc2[i][q] = 0ull;
#pragma unroll
        for (int nn = 0; nn < 32; nn += 4) {
            int n = kg * 32 + nn;
            float4 b0 = *(const float4*)&y2s[(dg +  0) * 260 + n];
            float4 b1 = *(const float4*)&y2s[(dg +  8) * 260 + n];
            float4 b2 = *(const float4*)&y2s[(dg + 16) * 260 + n];
            float4 b3 = *(const float4*)&y2s[(dg + 24) * 260 + n];
            float bv[4][4] = {{b0.x, b0.y, b0.z, b0.w}, {b1.x, b1.y, b1.z, b1.w},
                              {b2.x, b2.y, b2.z, b2.w}, {b3.x, b3.y, b3.z, b3.w}};
#pragma unroll
            for (int j = 0; j < 4; j++) {
                ulonglong2 s0 = *(const ulonglong2*)&ss[(n + j) * 36 + mq * 8];
                ulonglong2 s1 = *(const ulonglong2*)&ss[(n + j) * 36 + mq * 8 + 4];
#pragma unroll
                for (int i = 0; i < 4; i++) {
                    unsigned long long ar = pk2(bv[i][j], bv[i][j]);
                    acc2[i][0] = ffma2(ar, s0.x, acc2[i][0]);
                    acc2[i][1] = ffma2(ar, s0.y, acc2[i][1]);
                    acc2[i][2] = ffma2(ar, s1.x, acc2[i][2]);
                    acc2[i][3] = ffma2(ar, s1.y, acc2[i][3]);
                }
            }
        }
        __syncthreads();  // y1s/xrs fully consumed; safe to overlay sp
#pragma unroll
        for (int i = 0; i < 4; i++) {
            float* dst = &sp[kg * 1152 + (dg + 8 * i) * 36 + mq * 8];
            *(ulonglong2*)dst       = make_ulonglong2(acc2[i][0], acc2[i][1]);
            *(ulonglong2*)(dst + 4) = make_ulonglong2(acc2[i][2], acc2[i][3]);
        }
        __syncthreads();

        // ---- reduce 8 partials + LIF3 + store ----
        float4 sum = make_float4(v3[0], v3[1], v3[2], v3[3]);
#pragma unroll
        for (int k = 0; k < 8; k++) {
            float4 p = *(const float4*)&sp[k * 1152 + rd * 36 + rm];
            sum.x += p.x; sum.y += p.y; sum.z += p.z; sum.w += p.w;
        }
        sum.x *= 0.5f; sum.y *= 0.5f; sum.z *= 0.5f; sum.w *= 0.5f;
        float4 so;
        so.x = (sum.x >= 1.0f) ? 1.0f : 0.0f; v3[0] = (sum.x >= 1.0f) ? 0.0f : sum.x;
        so.y = (sum.y >= 1.0f) ? 1.0f : 0.0f; v3[1] = (sum.y >= 1.0f) ? 0.0f : sum.y;
        so.z = (sum.z >= 1.0f) ? 1.0f : 0.0f; v3[2] = (sum.z >= 1.0f) ? 0.0f : sum.z;
        so.w = (sum.w >= 1.0f) ? 1.0f : 0.0f; v3[3] = (sum.w >= 1.0f) ? 0.0f : sum.w;
        *(float4*)&g_sp3[((size_t)img * 384 + h * 32 + rd) * 1024 + mt * 32 + rm] = so;
        __syncthreads();  // sp region reused as y1s next t
    }
}

// ============================================================
// Kernel D: proj GEMM (384x16384, K=384) + BN2 + residual
// ============================================================
__global__ void __launch_bounds__(256, 2) proj_kernel(
    const float* __restrict__ Wp, const float* __restrict__ g2,
    const float* __restrict__ b2v, const float* __restrict__ x,
    float* __restrict__ out)
{
    __shared__ __align__(16) float As[2][16][128];
    __shared__ __align__(16) float Bs[2][16][128];
    const int bx = blockIdx.x;
    const int nt = bx & 127;
    const int ot = bx >> 7;
    const int tid = threadIdx.x;
    const int tx = tid & 15, ty = tid >> 4;
    const int obase = ot * 128;
    const int tb = nt >> 3;
    const int hw0 = (nt & 7) * 128;
    const int oA = tid & 127, kh2 = tid >> 7;
    const float bnA = g2[obase + oA] * rsqrtf(1.0f + EPSF);

    unsigned long long acc[8][4];
#pragma unroll
    for (int r = 0; r < 8; r++)
#pragma unroll
        for (int q = 0; q < 4; q++) acc[r][q] = 0ull;

    auto ldA = [&](int kc, int buf) {
#pragma unroll
        for (int v = 0; v < 2; v++) {
            float4 w = *(const float4*)&Wp[(size_t)(obase + oA) * 384 + kc + kh2 * 8 + v * 4];
            As[buf][kh2 * 8 + v * 4 + 0][oA] = w.x * bnA;
            As[buf][kh2 * 8 + v * 4 + 1][oA] = w.y * bnA;
            As[buf][kh2 * 8 + v * 4 + 2][oA] = w.z * bnA;
            As[buf][kh2 * 8 + v * 4 + 3][oA] = w.w * bnA;
        }
    };
    auto ldB = [&](int kc, int buf) {
#pragma unroll
        for (int r = 0; r < 2; r++) {
            int e = tid + 256 * r;
            int k = e >> 5, p4 = e & 31;
            *(float4*)&Bs[buf][k][p4 * 4] =
                *(const float4*)&g_sp3[((size_t)(tb * 384 + kc + k)) * 1024 + hw0 + p4 * 4];
        }
    };

    int buf = 0;
    ldA(0, 0); ldB(0, 0);
    __syncthreads();
    for (int kc = 0; kc < 384; kc += 16) {
        if (kc + 16 < 384) { ldA(kc + 16, buf ^ 1); ldB(kc + 16, buf ^ 1); }
#pragma unroll
        for (int k = 0; k < 16; k++) {
            float4 a0 = *(const float4*)&As[buf][k][ty * 8];
            float4 a1 = *(const float4*)&As[buf][k][ty * 8 + 4];
            ulonglong2 b0 = *(const ulonglong2*)&Bs[buf][k][tx * 8];
            ulonglong2 b1 = *(const ulonglong2*)&Bs[buf][k][tx * 8 + 4];
            float av[8] = {a0.x, a0.y, a0.z, a0.w, a1.x, a1.y, a1.z, a1.w};
#pragma unroll
            for (int r = 0; r < 8; r++) {
                unsigned long long ar = pk2(av[r], av[r]);
                acc[r][0] = ffma2(ar, b0.x, acc[r][0]);
                acc[r][1] = ffma2(ar, b0.y, acc[r][1]);
                acc[r][2] = ffma2(ar, b1.x, acc[r][2]);
                acc[r][3] = ffma2(ar, b1.y, acc[r][3]);
            }
        }
        __syncthreads();
        buf ^= 1;
    }

#pragma unroll
    for (int r = 0; r < 8; r++) {
        int o = obase + ty * 8 + r;
        size_t idx = ((size_t)tb * 384 + o) * 1024 + hw0 + tx * 8;
        float4 xv0 = *(const float4*)&x[idx];
        float4 xv1 = *(const float4*)&x[idx + 4];
        float bt = b2v[o];
        float v0, v1, v2, v3, v4, v5, v6, v7;
        upk2(acc[r][0], v0, v1); upk2(acc[r][1], v2, v3);
        upk2(acc[r][2], v4, v5); upk2(acc[r][3], v6, v7);
        *(float4*)&out[idx]     = make_float4(v0 + bt + xv0.x, v1 + bt + xv0.y,
                                              v2 + bt + xv0.z, v3 + bt + xv0.w);
        *(float4*)&out[idx + 4] = make_float4(v4 + bt + xv1.x, v5 + bt + xv1.y,
                                              v6 + bt + xv1.z, v7 + bt + xv1.w);
    }
}

// ============================================================
extern "C" void kernel_launch(void* const* d_in, const int* in_sizes, int n_in,
                              void* d_out, int out_size) {
    const float* x   = (const float*)d_in[0];
    const float* Wc  = (const float*)d_in[1];
    const float* g1  = (const float*)d_in[2];
    const float* b1  = (const float*)d_in[3];
    const float* Wp  = (const float*)d_in[4];
    const float* g2  = (const float*)d_in[5];
    const float* b2  = (const float*)d_in[6];
    const float* frx = (const float*)d_in[7];
    const float* fra = (const float*)d_in[8];
    float* out = (float*)d_out;

    const int smem_attn = 26752 * 4;  // 107,008 B
    cudaFuncSetAttribute(attn_fused_kernel,
                         cudaFuncAttributeMaxDynamicSharedMemorySize, smem_attn);

    lif1_kernel<<<6144, 256>>>(x);
    conv_partial_kernel<<<576, 256>>>(Wc);
    reduce_bn_kernel<<<3072, 256>>>(g1, b1);
    attn_fused_kernel<<<1536, 256, smem_attn>>>(frx, fra);
    proj_kernel<<<384, 256>>>(Wp, g2, b2, x, out);
}

// round 6
// speedup vs baseline: 1.7999x; 1.2886x over previous
#include <cuda_runtime.h>
#include <cuda_bf16.h>

#define EPSF 1e-5f
typedef unsigned short u16;
typedef unsigned int u32;
typedef unsigned long long u64;

// ---------------- device scratch ----------------
static __device__ float g_xs  [6291456];  // LIF1 spikes f32 (T,B,C,H,W)
static __device__ u16   g_xsb [6291456];  // conv B: bf16 im2col [img][p=256][k=1536]
static __device__ float g_y   [3145728];  // conv+BN output f32 [img][768][256]
static __device__ u16   g_sp3b[6291456];  // LIF3 spikes bf16 [img][c=384][hw=1024]
static __device__ u16   g_sp3T[6291456];  // transposed bf16 [img][hw=1024][c=384]
static __device__ u16   g_wc3 [3538944];  // Wconv 3-term bf16 split [3][768][1536]
static __device__ u16   g_wp3 [442368];   // Wproj 3-term bf16 split [3][384][384]

// ---------------- fp32x2 helpers ----------------
__device__ __forceinline__ u64 pk2(float lo, float hi) {
    u64 r; asm("mov.b64 %0, {%1,%2};" : "=l"(r) : "f"(lo), "f"(hi)); return r;
}
__device__ __forceinline__ void upk2(u64 v, float& lo, float& hi) {
    asm("mov.b64 {%0,%1}, %2;" : "=f"(lo), "=f"(hi) : "l"(v));
}
__device__ __forceinline__ u64 ffma2(u64 a, u64 b, u64 c) {
    u64 d; asm("fma.rn.f32x2 %0, %1, %2, %3;" : "=l"(d) : "l"(a), "l"(b), "l"(c)); return d;
}

// ---------------- mma.sync bf16 helper ----------------
__device__ __forceinline__ void mma16816(
    float& c0, float& c1, float& c2, float& c3,
    u32 a0, u32 a1, u32 a2, u32 a3, u32 b0, u32 b1)
{
    asm volatile(
        "mma.sync.aligned.m16n8k16.row.col.f32.bf16.bf16.f32 "
        "{%0,%1,%2,%3}, {%4,%5,%6,%7}, {%8,%9}, {%0,%1,%2,%3};"
        : "+f"(c0), "+f"(c1), "+f"(c2), "+f"(c3)
        : "r"(a0), "r"(a1), "r"(a2), "r"(a3), "r"(b0), "r"(b1));
}

// ============================================================
// Kernel A: LIF over T on x -> spikes g_xs (f32)
// ============================================================
__global__ void __launch_bounds__(256) lif1_kernel(const float* __restrict__ x) {
    const int S = 4 * 384 * 1024;
    int i = blockIdx.x * blockDim.x + threadIdx.x;
    if (i >= S) return;
    float v = 0.0f;
#pragma unroll
    for (int t = 0; t < 4; t++) {
        v = 0.5f * (v + x[(size_t)t * S + i]);
        bool s = (v >= 1.0f);
        g_xs[(size_t)t * S + i] = s ? 1.0f : 0.0f;
        v = s ? 0.0f : v;
    }
}

// ============================================================
// Kernel A2: im2col bf16 for conv B: g_xs -> g_xsb[img][p][k]
// k = c*4 + kh*2 + kw
// ============================================================
__global__ void __launch_bounds__(256) im2col_kernel() {
    int idx = blockIdx.x * 256 + threadIdx.x;   // 16*384*256 = 1,572,864
    int img = idx / 98304;
    int r = idx - img * 98304;
    int c = r >> 8;
    int pp = r & 255;
    int ii = pp >> 4, jj = pp & 15;
    const float* base = g_xs + (size_t)img * 393216 + c * 1024;
    float2 a = *(const float2*)&base[(2 * ii) * 32 + 2 * jj];
    float2 b = *(const float2*)&base[(2 * ii + 1) * 32 + 2 * jj];
    ushort4 o;
    o.x = (a.x > 0.5f) ? 0x3F80 : 0;
    o.y = (a.y > 0.5f) ? 0x3F80 : 0;
    o.z = (b.x > 0.5f) ? 0x3F80 : 0;
    o.w = (b.y > 0.5f) ? 0x3F80 : 0;
    *(ushort4*)&g_xsb[((size_t)img * 256 + pp) * 1536 + c * 4] = o;
}

// ============================================================
// Kernel W: split fp32 weights into 3 bf16 terms (Dekker, exact)
// ============================================================
__global__ void __launch_bounds__(256) wsplit_kernel(
    const float* __restrict__ Wc, const float* __restrict__ Wp)
{
    int i = blockIdx.x * 256 + threadIdx.x;  // 1,327,104 = 5184*256 exact
    float w;
    u16* d;
    int n, off;
    if (i < 1179648) { off = i; w = Wc[off]; d = g_wc3; n = 1179648; }
    else             { off = i - 1179648; w = Wp[off]; d = g_wp3; n = 147456; }
    __nv_bfloat16 h = __float2bfloat16(w);
    float r1 = w - __bfloat162float(h);
    __nv_bfloat16 m = __float2bfloat16(r1);
    float r2 = r1 - __bfloat162float(m);
    __nv_bfloat16 l = __float2bfloat16(r2);
    d[off]         = __bfloat16_as_ushort(h);
    d[n + off]     = __bfloat16_as_ushort(m);
    d[2 * n + off] = __bfloat16_as_ushort(l);
}

// ============================================================
// Kernel B: conv as mma.sync GEMM + BN1.
// CTA tile 128(o) x 128(p), K=1536 in 48 chunks of 32.
// grid 192 (16 img x 6 ot x 2 pt), 256 threads, 80KB smem.
// smem per buf (u32): A 3*128*20=7680, B 128*20=2560 -> 10240
// ============================================================
__global__ void __launch_bounds__(256) conv_mma_kernel(
    const float* __restrict__ g1, const float* __restrict__ b1)
{
    extern __shared__ u32 smu[];
    const int tid = threadIdx.x;
    const int wid = tid >> 5, lane = tid & 31;
    const int g = lane >> 2, t = lane & 3;
    const int wm = wid >> 2, wn = wid & 3;
    const int bx = blockIdx.x;
    const int img = bx / 12;
    const int r12 = bx % 12;
    const int ot = r12 >> 1, pt = r12 & 1;
    const int obase = ot * 128, pbase = pt * 128;
    const u16* Asrc = g_wc3;
    const u16* Bsrc = g_xsb + ((size_t)img * 256 + pbase) * 1536;

    float acc[4][4][4];
#pragma unroll
    for (int mt = 0; mt < 4; mt++)
#pragma unroll
        for (int nt = 0; nt < 4; nt++)
#pragma unroll
            for (int q = 0; q < 4; q++) acc[mt][nt][q] = 0.0f;

    auto ldChunk = [&](int c, int buf) {
        u32* S = smu + buf * 10240;
        int k0 = c * 32;
#pragma unroll
        for (int it = 0; it < 6; it++) {
            int e = tid + 256 * it;          // 0..1535
            int j = e >> 9;
            int r = (e >> 2) & 127;
            int kg = e & 3;
            uint4 v = *(const uint4*)&Asrc[(size_t)j * 1179648
                                           + (size_t)(obase + r) * 1536 + k0 + kg * 8];
            *(uint4*)&S[j * 2560 + r * 20 + kg * 4] = v;
        }
#pragma unroll
        for (int it = 0; it < 2; it++) {
            int e = tid + 256 * it;          // 0..511
            int r = e >> 2, kg = e & 3;
            uint4 v = *(const uint4*)&Bsrc[(size_t)r * 1536 + k0 + kg * 8];
            *(uint4*)&S[7680 + r * 20 + kg * 4] = v;
        }
    };

    ldChunk(0, 0);
    __syncthreads();
    for (int c = 0; c < 48; c++) {
        int buf = c & 1;
        if (c + 1 < 48) ldChunk(c + 1, buf ^ 1);
        const u32* S = smu + buf * 10240;
#pragma unroll
        for (int k16 = 0; k16 < 2; k16++) {
            u32 bf[4][2];
#pragma unroll
            for (int nt = 0; nt < 4; nt++) {
                int n = wn * 32 + nt * 8 + g;
                bf[nt][0] = S[7680 + n * 20 + k16 * 8 + t];
                bf[nt][1] = S[7680 + n * 20 + k16 * 8 + t + 4];
            }
#pragma unroll
            for (int j = 0; j < 3; j++) {
                const u32* SA = S + j * 2560;
#pragma unroll
                for (int mt = 0; mt < 4; mt++) {
                    int r0 = wm * 64 + mt * 16 + g;
                    u32 a0 = SA[r0 * 20 + k16 * 8 + t];
                    u32 a1 = SA[(r0 + 8) * 20 + k16 * 8 + t];
                    u32 a2 = SA[r0 * 20 + k16 * 8 + t + 4];
                    u32 a3 = SA[(r0 + 8) * 20 + k16 * 8 + t + 4];
#pragma unroll
                    for (int nt = 0; nt < 4; nt++)
                        mma16816(acc[mt][nt][0], acc[mt][nt][1],
                                 acc[mt][nt][2], acc[mt][nt][3],
                                 a0, a1, a2, a3, bf[nt][0], bf[nt][1]);
                }
            }
        }
        __syncthreads();
    }

    const float rs = rsqrtf(1.0f + EPSF);
#pragma unroll
    for (int mt = 0; mt < 4; mt++) {
        int o0 = obase + wm * 64 + mt * 16 + g;
        int o1 = o0 + 8;
        float bn0 = g1[o0] * rs, bt0 = b1[o0];
        float bn1 = g1[o1] * rs, bt1 = b1[o1];
#pragma unroll
        for (int nt = 0; nt < 4; nt++) {
            int p = pbase + wn * 32 + nt * 8 + 2 * t;
            float2 v0 = make_float2(acc[mt][nt][0] * bn0 + bt0,
                                    acc[mt][nt][1] * bn0 + bt0);
            float2 v1 = make_float2(acc[mt][nt][2] * bn1 + bt1,
                                    acc[mt][nt][3] * bn1 + bt1);
            *(float2*)&g_y[((size_t)img * 768 + o0) * 256 + p] = v0;
            *(float2*)&g_y[((size_t)img * 768 + o1) * 256 + p] = v1;
        }
    }
}

// ============================================================
// Kernel C: fused attn GEMM -> LIF2 -> out GEMM(ksplit8) -> LIF3
// grid 1536, 256 threads. Emits bf16 spikes (g_sp3b).
// ============================================================
__global__ void __launch_bounds__(256, 2) attn_fused_kernel(
    const float* __restrict__ frx, const float* __restrict__ fra)
{
    extern __shared__ __align__(16) float sm[];
    float* y1s = sm;
    float* xrs = sm + 8192;
    float* y2s = sm + 9216;
    float* ss  = sm + 17536;
    float* sp  = sm;  // overlay

    const int bx = blockIdx.x;
    const int mt = bx & 31;
    const int h  = (bx >> 5) % 12;
    const int b  = bx / 384;
    const int tid = threadIdx.x;

    const int ng = tid >> 2;
    const int mg = tid & 3;
    const int n0 = ng * 4, m0 = mg * 8;
    const int kg = tid >> 5;
    const int lane = tid & 31;
    const int dg = lane >> 2;
    const int mq = lane & 3;
    const int rd = tid >> 3;
    const int rm = (tid & 7) * 4;

    const float scale1 = rsqrtf(frx[h] * 32.0f);
    const float scale2 = rsqrtf(fra[h] * 256.0f);

    float v2[4][8];
    float v3[4];
#pragma unroll
    for (int i = 0; i < 4; i++)
#pragma unroll
        for (int j = 0; j < 8; j++) v2[i][j] = 0.0f;
#pragma unroll
    for (int i = 0; i < 4; i++) v3[i] = 0.0f;

    for (int t = 0; t < 4; t++) {
        const int img = t * 4 + b;
        const float* ybase = g_y + ((size_t)img * 768 + h * 64) * 256;
#pragma unroll
        for (int r = 0; r < 8; r++) {
            int e = tid + 256 * r;
            int d = e >> 6, c4 = (e & 63) * 4;
            float4 w = *(const float4*)&ybase[d * 256 + c4];
            *(float4*)&y1s[d * 256 + c4] = make_float4(
                w.x * scale1, w.y * scale1, w.z * scale1, w.w * scale1);
        }
#pragma unroll
        for (int r = 0; r < 8; r++) {
            int e = tid + 256 * r;
            int d = e >> 6, c4 = (e & 63) * 4;
            float4 w = *(const float4*)&ybase[(32 + d) * 256 + c4];
            *(float4*)&y2s[d * 260 + c4] = make_float4(
                w.x * scale2, w.y * scale2, w.z * scale2, w.w * scale2);
        }
        {
            const float* xbase = g_xs + ((size_t)img * 384 + h * 32) * 1024 + mt * 32;
            int d = tid >> 3, c4 = (tid & 7) * 4;
            *(float4*)&xrs[d * 32 + c4] = *(const float4*)&xbase[d * 1024 + c4];
        }
        __syncthreads();

        // GEMM1
        u64 acc[4][4];
#pragma unroll
        for (int i = 0; i < 4; i++)
#pragma unroll
            for (int q = 0; q < 4; q++) acc[i][q] = pk2(v2[i][2 * q], v2[i][2 * q + 1]);
#pragma unroll 8
        for (int d = 0; d < 32; d++) {
            float4 a4 = *(const float4*)&y1s[d * 256 + n0];
            ulonglong2 x0 = *(const ulonglong2*)&xrs[d * 32 + m0];
            ulonglong2 x1 = *(const ulonglong2*)&xrs[d * 32 + m0 + 4];
            float av[4] = {a4.x, a4.y, a4.z, a4.w};
#pragma unroll
            for (int i = 0; i < 4; i++) {
                u64 ar = pk2(av[i], av[i]);
                acc[i][0] = ffma2(ar, x0.x, acc[i][0]);
                acc[i][1] = ffma2(ar, x0.y, acc[i][1]);
                acc[i][2] = ffma2(ar, x1.x, acc[i][2]);
                acc[i][3] = ffma2(ar, x1.y, acc[i][3]);
            }
        }
        // LIF2
#pragma unroll
        for (int i = 0; i < 4; i++) {
            float s[8];
#pragma unroll
            for (int q = 0; q < 4; q++) {
                float lo, hi;
                upk2(acc[i][q], lo, hi);
                lo *= 0.5f; hi *= 0.5f;
                s[2 * q]     = (lo >= 1.0f) ? 1.0f : 0.0f;
                s[2 * q + 1] = (hi >= 1.0f) ? 1.0f : 0.0f;
                v2[i][2 * q]     = (lo >= 1.0f) ? 0.0f : lo;
                v2[i][2 * q + 1] = (hi >= 1.0f) ? 0.0f : hi;
            }
            *(float4*)&ss[(n0 + i) * 36 + m0]     = make_float4(s[0], s[1], s[2], s[3]);
            *(float4*)&ss[(n0 + i) * 36 + m0 + 4] = make_float4(s[4], s[5], s[6], s[7]);
        }
        __syncthreads();

        // GEMM2 (ksplit 8)
        u64 acc2[4][4];
#pragma unroll
        for (int i = 0; i < 4; i++)
#pragma unroll
            for (int q = 0; q < 4; q++) acc2[i][q] = 0ull;
#pragma unroll
        for (int nn = 0; nn < 32; nn += 4) {
            int n = kg * 32 + nn;
            float4 b0 = *(const float4*)&y2s[(dg +  0) * 260 + n];
            float4 b1 = *(const float4*)&y2s[(dg +  8) * 260 + n];
            float4 b2 = *(const float4*)&y2s[(dg + 16) * 260 + n];
            float4 b3 = *(const float4*)&y2s[(dg + 24) * 260 + n];
            float bv[4][4] = {{b0.x, b0.y, b0.z, b0.w}, {b1.x, b1.y, b1.z, b1.w},
                              {b2.x, b2.y, b2.z, b2.w}, {b3.x, b3.y, b3.z, b3.w}};
#pragma unroll
            for (int j = 0; j < 4; j++) {
                ulonglong2 s0 = *(const ulonglong2*)&ss[(n + j) * 36 + mq * 8];
                ulonglong2 s1 = *(const ulonglong2*)&ss[(n + j) * 36 + mq * 8 + 4];
#pragma unroll
                for (int i = 0; i < 4; i++) {
                    u64 ar = pk2(bv[i][j], bv[i][j]);
                    acc2[i][0] = ffma2(ar, s0.x, acc2[i][0]);
                    acc2[i][1] = ffma2(ar, s0.y, acc2[i][1]);
                    acc2[i][2] = ffma2(ar, s1.x, acc2[i][2]);
                    acc2[i][3] = ffma2(ar, s1.y, acc2[i][3]);
                }
            }
        }
        __syncthreads();
#pragma unroll
        for (int i = 0; i < 4; i++) {
            float* dst = &sp[kg * 1152 + (dg + 8 * i) * 36 + mq * 8];
            *(ulonglong2*)dst       = make_ulonglong2(acc2[i][0], acc2[i][1]);
            *(ulonglong2*)(dst + 4) = make_ulonglong2(acc2[i][2], acc2[i][3]);
        }
        __syncthreads();

        // reduce + LIF3 + bf16 spike store
        float4 sum = make_float4(v3[0], v3[1], v3[2], v3[3]);
#pragma unroll
        for (int k = 0; k < 8; k++) {
            float4 p = *(const float4*)&sp[k * 1152 + rd * 36 + rm];
            sum.x += p.x; sum.y += p.y; sum.z += p.z; sum.w += p.w;
        }
        sum.x *= 0.5f; sum.y *= 0.5f; sum.z *= 0.5f; sum.w *= 0.5f;
        ushort4 sb;
        sb.x = (sum.x >= 1.0f) ? 0x3F80 : 0; v3[0] = (sum.x >= 1.0f) ? 0.0f : sum.x;
        sb.y = (sum.y >= 1.0f) ? 0x3F80 : 0; v3[1] = (sum.y >= 1.0f) ? 0.0f : sum.y;
        sb.z = (sum.z >= 1.0f) ? 0x3F80 : 0; v3[2] = (sum.z >= 1.0f) ? 0.0f : sum.z;
        sb.w = (sum.w >= 1.0f) ? 0x3F80 : 0; v3[3] = (sum.w >= 1.0f) ? 0.0f : sum.w;
        *(ushort4*)&g_sp3b[((size_t)img * 384 + h * 32 + rd) * 1024 + mt * 32 + rm] = sb;
        __syncthreads();
    }
}

// ============================================================
// Kernel T: transpose bf16 spikes [c][hw] -> [hw][c] per img
// ============================================================
__global__ void __launch_bounds__(256) transpose_sp3_kernel() {
    __shared__ u16 ts[64][72];
    int bx = blockIdx.x;
    int img = bx / 96;
    int r = bx % 96;
    int c0 = (r / 16) * 64;
    int hw0 = (r % 16) * 64;
    int tid = threadIdx.x;
#pragma unroll
    for (int it = 0; it < 4; it++) {
        int e = tid + 256 * it;
        int row = e >> 4, q = e & 15;
        u64 v = *(const u64*)&g_sp3b[((size_t)img * 384 + c0 + row) * 1024 + hw0 + q * 4];
        *(u64*)&ts[row][q * 4] = v;
    }
    __syncthreads();
#pragma unroll
    for (int it = 0; it < 4; it++) {
        int e = tid + 256 * it;
        int orow = e >> 4, q = e & 15;
        u64 v = (u64)ts[q * 4 + 0][orow]
              | ((u64)ts[q * 4 + 1][orow] << 16)
              | ((u64)ts[q * 4 + 2][orow] << 32)
              | ((u64)ts[q * 4 + 3][orow] << 48);
        *(u64*)&g_sp3T[((size_t)img * 1024 + hw0 + orow) * 384 + c0 + q * 4] = v;
    }
}

// ============================================================
// Kernel D: proj as mma.sync GEMM + BN2 + residual.
// CTA tile 128(o) x 128(hw), K=384 in 12 chunks of 32.
// grid 384 (3 ot x 128 nt), 256 threads, 80KB smem.
// ============================================================
__global__ void __launch_bounds__(256) proj_mma_kernel(
    const float* __restrict__ g2, const float* __restrict__ b2v,
    const float* __restrict__ x, float* __restrict__ out)
{
    extern __shared__ u32 smu[];
    const int tid = threadIdx.x;
    const int wid = tid >> 5, lane = tid & 31;
    const int g = lane >> 2, t = lane & 3;
    const int wm = wid >> 2, wn = wid & 3;
    const int bx = blockIdx.x;
    const int ot = bx >> 7;
    const int nt = bx & 127;
    const int obase = ot * 128;
    const int img = nt >> 3;
    const int hw0 = (nt & 7) * 128;
    const u16* Asrc = g_wp3;
    const u16* Bsrc = g_sp3T + ((size_t)img * 1024 + hw0) * 384;

    float acc[4][4][4];
#pragma unroll
    for (int mt = 0; mt < 4; mt++)
#pragma unroll
        for (int ntt = 0; ntt < 4; ntt++)
#pragma unroll
            for (int q = 0; q < 4; q++) acc[mt][ntt][q] = 0.0f;

    auto ldChunk = [&](int c, int buf) {
        u32* S = smu + buf * 10240;
        int k0 = c * 32;
#pragma unroll
        for (int it = 0; it < 6; it++) {
            int e = tid + 256 * it;
            int j = e >> 9;
            int r = (e >> 2) & 127;
            int kg = e & 3;
            uint4 v = *(const uint4*)&Asrc[(size_t)j * 147456
                                           + (size_t)(obase + r) * 384 + k0 + kg * 8];
            *(uint4*)&S[j * 2560 + r * 20 + kg * 4] = v;
        }
#pragma unroll
        for (int it = 0; it < 2; it++) {
            int e = tid + 256 * it;
            int r = e >> 2, kg = e & 3;
            uint4 v = *(const uint4*)&Bsrc[(size_t)r * 384 + k0 + kg * 8];
            *(uint4*)&S[7680 + r * 20 + kg * 4] = v;
        }
    };

    ldChunk(0, 0);
    __syncthreads();
    for (int c = 0; c < 12; c++) {
        int buf = c & 1;
        if (c + 1 < 12) ldChunk(c + 1, buf ^ 1);
        const u32* S = smu + buf * 10240;
#pragma unroll
        for (int k16 = 0; k16 < 2; k16++) {
            u32 bf[4][2];
#pragma unroll
            for (int ntt = 0; ntt < 4; ntt++) {
                int n = wn * 32 + ntt * 8 + g;
                bf[ntt][0] = S[7680 + n * 20 + k16 * 8 + t];
                bf[ntt][1] = S[7680 + n * 20 + k16 * 8 + t + 4];
            }
#pragma unroll
            for (int j = 0; j < 3; j++) {
                const u32* SA = S + j * 2560;
#pragma unroll
                for (int mt = 0; mt < 4; mt++) {
                    int r0 = wm * 64 + mt * 16 + g;
                    u32 a0 = SA[r0 * 20 + k16 * 8 + t];
                    u32 a1 = SA[(r0 + 8) * 20 + k16 * 8 + t];
                    u32 a2 = SA[r0 * 20 + k16 * 8 + t + 4];
                    u32 a3 = SA[(r0 + 8) * 20 + k16 * 8 + t + 4];
#pragma unroll
                    for (int ntt = 0; ntt < 4; ntt++)
                        mma16816(acc[mt][ntt][0], acc[mt][ntt][1],
                                 acc[mt][ntt][2], acc[mt][ntt][3],
                                 a0, a1, a2, a3, bf[ntt][0], bf[ntt][1]);
                }
            }
        }
        __syncthreads();
    }

    const float rs = rsqrtf(1.0f + EPSF);
#pragma unroll
    for (int mt = 0; mt < 4; mt++) {
        int o0 = obase + wm * 64 + mt * 16 + g;
        int o1 = o0 + 8;
        float bn0 = g2[o0] * rs, bt0 = b2v[o0];
        float bn1 = g2[o1] * rs, bt1 = b2v[o1];
#pragma unroll
        for (int ntt = 0; ntt < 4; ntt++) {
            int col = hw0 + wn * 32 + ntt * 8 + 2 * t;
            size_t i0 = ((size_t)img * 384 + o0) * 1024 + col;
            size_t i1 = ((size_t)img * 384 + o1) * 1024 + col;
            float2 x0 = *(const float2*)&x[i0];
            float2 x1 = *(const float2*)&x[i1];
            float2 v0 = make_float2(acc[mt][ntt][0] * bn0 + bt0 + x0.x,
                                    acc[mt][ntt][1] * bn0 + bt0 + x0.y);
            float2 v1 = make_float2(acc[mt][ntt][2] * bn1 + bt1 + x1.x,
                                    acc[mt][ntt][3] * bn1 + bt1 + x1.y);
            *(float2*)&out[i0] = v0;
            *(float2*)&out[i1] = v1;
        }
    }
}

// ============================================================
extern "C" void kernel_launch(void* const* d_in, const int* in_sizes, int n_in,
                              void* d_out, int out_size) {
    const float* x   = (const float*)d_in[0];
    const float* Wc  = (const float*)d_in[1];
    const float* g1  = (const float*)d_in[2];
    const float* b1  = (const float*)d_in[3];
    const float* Wp  = (const float*)d_in[4];
    const float* g2  = (const float*)d_in[5];
    const float* b2  = (const float*)d_in[6];
    const float* frx = (const float*)d_in[7];
    const float* fra = (const float*)d_in[8];
    float* out = (float*)d_out;

    const int smem_attn = 26752 * 4;   // 107,008 B
    const int smem_mma  = 81920;       // 2 x 40KB double buffer
    cudaFuncSetAttribute(attn_fused_kernel,
                         cudaFuncAttributeMaxDynamicSharedMemorySize, smem_attn);
    cudaFuncSetAttribute(conv_mma_kernel,
                         cudaFuncAttributeMaxDynamicSharedMemorySize, smem_mma);
    cudaFuncSetAttribute(proj_mma_kernel,
                         cudaFuncAttributeMaxDynamicSharedMemorySize, smem_mma);

    lif1_kernel<<<6144, 256>>>(x);
    im2col_kernel<<<6144, 256>>>();
    wsplit_kernel<<<5184, 256>>>(Wc, Wp);
    conv_mma_kernel<<<192, 256, smem_mma>>>(g1, b1);
    attn_fused_kernel<<<1536, 256, smem_attn>>>(frx, fra);
    transpose_sp3_kernel<<<1536, 256>>>();
    proj_mma_kernel<<<384, 256, smem_mma>>>(g2, b2, x, out);
}

// round 7
// speedup vs baseline: 2.2271x; 1.2374x over previous
#include <cuda_runtime.h>
#include <cuda_bf16.h>

#define EPSF 1e-5f
typedef unsigned short u16;
typedef unsigned int u32;
typedef unsigned long long u64;

// ---------------- device scratch ----------------
static __device__ __align__(256) float g_xs  [6291456];  // LIF1 spikes f32
static __device__ __align__(256) u16   g_xsb [6291456];  // conv B bf16 im2col [img][p][k]
static __device__ __align__(256) float g_y   [3145728];  // conv+BN output f32
static __device__ __align__(256) float g_yp  [3][3145728]; // conv K-split partials
static __device__ __align__(256) u16   g_sp3b[6291456];  // LIF3 spikes bf16 [img][c][hw]
static __device__ __align__(256) u16   g_sp3T[6291456];  // transposed [img][hw][c]
static __device__ __align__(256) u16   g_wc3 [3538944];  // Wconv 3-term bf16 [3][768][1536]
static __device__ __align__(256) u16   g_wp3 [442368];   // Wproj 3-term bf16 [3][384][384]

// ---------------- fp32x2 helpers ----------------
__device__ __forceinline__ u64 pk2(float lo, float hi) {
    u64 r; asm("mov.b64 %0, {%1,%2};" : "=l"(r) : "f"(lo), "f"(hi)); return r;
}
__device__ __forceinline__ void upk2(u64 v, float& lo, float& hi) {
    asm("mov.b64 {%0,%1}, %2;" : "=f"(lo), "=f"(hi) : "l"(v));
}
__device__ __forceinline__ u64 ffma2(u64 a, u64 b, u64 c) {
    u64 d; asm("fma.rn.f32x2 %0, %1, %2, %3;" : "=l"(d) : "l"(a), "l"(b), "l"(c)); return d;
}

// ---------------- mma / ldmatrix / cp.async helpers ----------------
__device__ __forceinline__ void mma16816(
    float& c0, float& c1, float& c2, float& c3,
    u32 a0, u32 a1, u32 a2, u32 a3, u32 b0, u32 b1)
{
    asm volatile(
        "mma.sync.aligned.m16n8k16.row.col.f32.bf16.bf16.f32 "
        "{%0,%1,%2,%3}, {%4,%5,%6,%7}, {%8,%9}, {%0,%1,%2,%3};"
        : "+f"(c0), "+f"(c1), "+f"(c2), "+f"(c3)
        : "r"(a0), "r"(a1), "r"(a2), "r"(a3), "r"(b0), "r"(b1));
}
__device__ __forceinline__ void ldm_x4(u32& r0, u32& r1, u32& r2, u32& r3, u32 addr) {
    asm volatile("ldmatrix.sync.aligned.m8n8.x4.shared.b16 {%0,%1,%2,%3}, [%4];"
                 : "=r"(r0), "=r"(r1), "=r"(r2), "=r"(r3) : "r"(addr));
}
__device__ __forceinline__ void cp16(u32 saddr, const void* g) {
    asm volatile("cp.async.cg.shared.global [%0], [%1], 16;" :: "r"(saddr), "l"(g));
}
#define CP_COMMIT() asm volatile("cp.async.commit_group;" ::: "memory")
#define CP_WAIT1()  asm volatile("cp.async.wait_group 1;" ::: "memory")
#define CP_WAIT0()  asm volatile("cp.async.wait_group 0;" ::: "memory")
__device__ __forceinline__ u32 smem_u32(const void* p) {
    u32 a;
    asm("{ .reg .u64 t; cvta.to.shared.u64 t, %1; cvt.u32.u64 %0, t; }" : "=r"(a) : "l"(p));
    return a;
}

// ============================================================
// Kernel A: LIF over T on x -> spikes g_xs (f32)
// ============================================================
__global__ void __launch_bounds__(256) lif1_kernel(const float* __restrict__ x) {
    const int S = 4 * 384 * 1024;
    int i = blockIdx.x * blockDim.x + threadIdx.x;
    if (i >= S) return;
    float v = 0.0f;
#pragma unroll
    for (int t = 0; t < 4; t++) {
        v = 0.5f * (v + x[(size_t)t * S + i]);
        bool s = (v >= 1.0f);
        g_xs[(size_t)t * S + i] = s ? 1.0f : 0.0f;
        v = s ? 0.0f : v;
    }
}

// ============================================================
// Kernel A2: im2col bf16 for conv B
// ============================================================
__global__ void __launch_bounds__(256) im2col_kernel() {
    int idx = blockIdx.x * 256 + threadIdx.x;
    int img = idx / 98304;
    int r = idx - img * 98304;
    int c = r >> 8;
    int pp = r & 255;
    int ii = pp >> 4, jj = pp & 15;
    const float* base = g_xs + (size_t)img * 393216 + c * 1024;
    float2 a = *(const float2*)&base[(2 * ii) * 32 + 2 * jj];
    float2 b = *(const float2*)&base[(2 * ii + 1) * 32 + 2 * jj];
    ushort4 o;
    o.x = (a.x > 0.5f) ? 0x3F80 : 0;
    o.y = (a.y > 0.5f) ? 0x3F80 : 0;
    o.z = (b.x > 0.5f) ? 0x3F80 : 0;
    o.w = (b.y > 0.5f) ? 0x3F80 : 0;
    *(ushort4*)&g_xsb[((size_t)img * 256 + pp) * 1536 + c * 4] = o;
}

// ============================================================
// Kernel W: split fp32 weights into 3 bf16 terms (Dekker, exact)
// ============================================================
__global__ void __launch_bounds__(256) wsplit_kernel(
    const float* __restrict__ Wc, const float* __restrict__ Wp)
{
    int i = blockIdx.x * 256 + threadIdx.x;
    float w;
    u16* d;
    int n, off;
    if (i < 1179648) { off = i; w = Wc[off]; d = g_wc3; n = 1179648; }
    else             { off = i - 1179648; w = Wp[off]; d = g_wp3; n = 147456; }
    __nv_bfloat16 h = __float2bfloat16(w);
    float r1 = w - __bfloat162float(h);
    __nv_bfloat16 m = __float2bfloat16(r1);
    float r2 = r1 - __bfloat162float(m);
    __nv_bfloat16 l = __float2bfloat16(r2);
    d[off]         = __bfloat16_as_ushort(h);
    d[n + off]     = __bfloat16_as_ushort(m);
    d[2 * n + off] = __bfloat16_as_ushort(l);
}

// ============================================================
// Kernel B: conv as mma.sync GEMM, K-split 3 -> fp32 partials.
// CTA tile 128(o) x 128(p); per ks: K=512 in 16 chunks of 32.
// grid 576 (3 ks x 16 img x 6 ot x 2 pt), 256 thr, 80KB smem.
// smem buf (u32): A 3*128*20=7680 | B 128*20=2560 -> 10240/buf
// ============================================================
__global__ void __launch_bounds__(256) conv_mma_kernel()
{
    extern __shared__ u32 smu[];
    const u32 sbase = smem_u32(smu);
    const int tid = threadIdx.x;
    const int wid = tid >> 5, lane = tid & 31;
    const int g = lane >> 2, t = lane & 3;
    const int wm = wid >> 2, wn = wid & 3;
    const int bx = blockIdx.x;
    const int ks = bx / 192;
    const int rem = bx % 192;
    const int img = rem / 12;
    const int r12 = rem % 12;
    const int ot = r12 >> 1, pt = r12 & 1;
    const int obase = ot * 128, pbase = pt * 128;
    const int kbase = ks * 512;
    const u16* Asrc = g_wc3;
    const u16* Bsrc = g_xsb + ((size_t)img * 256 + pbase) * 1536;

    float acc[4][4][4];
#pragma unroll
    for (int mt = 0; mt < 4; mt++)
#pragma unroll
        for (int nt = 0; nt < 4; nt++)
#pragma unroll
            for (int q = 0; q < 4; q++) acc[mt][nt][q] = 0.0f;

    auto ldChunk = [&](int c, int buf) {
        u32 sb = sbase + buf * 40960;
        int k0 = kbase + c * 32;
#pragma unroll
        for (int it = 0; it < 6; it++) {
            int e = tid + 256 * it;
            int j = e >> 9;
            int r = (e >> 2) & 127;
            int kg = e & 3;
            cp16(sb + (j * 2560 + r * 20 + kg * 4) * 4,
                 &Asrc[(size_t)j * 1179648 + (size_t)(obase + r) * 1536 + k0 + kg * 8]);
        }
#pragma unroll
        for (int it = 0; it < 2; it++) {
            int e = tid + 256 * it;
            int r = e >> 2, kg = e & 3;
            cp16(sb + (7680 + r * 20 + kg * 4) * 4,
                 &Bsrc[(size_t)r * 1536 + k0 + kg * 8]);
        }
        CP_COMMIT();
    };

    // fragment smem addresses (u32 words -> bytes)
    const int aRow = wm * 64 + (lane & 15);
    const int aColw = ((lane >> 4) & 1) * 4;
    const int bRow = wn * 32 + ((lane >> 4) & 1) * 8 + (lane & 7);
    const int bColw = ((lane >> 3) & 1) * 4;

    ldChunk(0, 0);
    for (int c = 0; c < 16; c++) {
        int buf = c & 1;
        if (c + 1 < 16) { ldChunk(c + 1, buf ^ 1); CP_WAIT1(); }
        else            { CP_WAIT0(); }
        __syncthreads();
        u32 soff = sbase + buf * 40960;
#pragma unroll
        for (int k16 = 0; k16 < 2; k16++) {
            u32 bfr[4][2];
#pragma unroll
            for (int ntp = 0; ntp < 2; ntp++) {
                u32 addr = soff + ((7680 + (bRow + ntp * 16) * 20 + k16 * 8 + bColw) << 2);
                ldm_x4(bfr[2 * ntp][0], bfr[2 * ntp][1],
                       bfr[2 * ntp + 1][0], bfr[2 * ntp + 1][1], addr);
            }
#pragma unroll
            for (int j = 0; j < 3; j++) {
#pragma unroll
                for (int mt = 0; mt < 4; mt++) {
                    u32 addr = soff + ((j * 2560 + (aRow + mt * 16) * 20 + k16 * 8 + aColw) << 2);
                    u32 a0, a1, a2, a3;
                    ldm_x4(a0, a1, a2, a3, addr);
#pragma unroll
                    for (int nt = 0; nt < 4; nt++)
                        mma16816(acc[mt][nt][0], acc[mt][nt][1],
                                 acc[mt][nt][2], acc[mt][nt][3],
                                 a0, a1, a2, a3, bfr[nt][0], bfr[nt][1]);
                }
            }
        }
        __syncthreads();
    }

    float* yo = g_yp[ks];
#pragma unroll
    for (int mt = 0; mt < 4; mt++) {
        int o0 = obase + wm * 64 + mt * 16 + g;
        int o1 = o0 + 8;
#pragma unroll
        for (int nt = 0; nt < 4; nt++) {
            int p = pbase + wn * 32 + nt * 8 + 2 * t;
            *(float2*)&yo[((size_t)img * 768 + o0) * 256 + p] =
                make_float2(acc[mt][nt][0], acc[mt][nt][1]);
            *(float2*)&yo[((size_t)img * 768 + o1) * 256 + p] =
                make_float2(acc[mt][nt][2], acc[mt][nt][3]);
        }
    }
}

// ============================================================
// Kernel B2: reduce 3 K-split partials + BN1 -> g_y
// ============================================================
__global__ void __launch_bounds__(256) reduce_bn_kernel(
    const float* __restrict__ g1, const float* __restrict__ b1)
{
    int i4 = blockIdx.x * 256 + threadIdx.x;
    const float4* p0 = (const float4*)g_yp[0];
    const float4* p1 = (const float4*)g_yp[1];
    const float4* p2 = (const float4*)g_yp[2];
    float4 a = p0[i4], b = p1[i4], c = p2[i4];
    int o = (i4 >> 6) % 768;
    const float rs = rsqrtf(1.0f + EPSF);
    float bn = g1[o] * rs, bt = b1[o];
    ((float4*)g_y)[i4] = make_float4(
        (a.x + b.x + c.x) * bn + bt,
        (a.y + b.y + c.y) * bn + bt,
        (a.z + b.z + c.z) * bn + bt,
        (a.w + b.w + c.w) * bn + bt);
}

// ============================================================
// Kernel C: fused attn GEMM -> LIF2 -> out GEMM(ksplit8) -> LIF3
// ============================================================
__global__ void __launch_bounds__(256, 2) attn_fused_kernel(
    const float* __restrict__ frx, const float* __restrict__ fra)
{
    extern __shared__ __align__(16) float sm[];
    float* y1s = sm;
    float* xrs = sm + 8192;
    float* y2s = sm + 9216;
    float* ss  = sm + 17536;
    float* sp  = sm;  // overlay

    const int bx = blockIdx.x;
    const int mt = bx & 31;
    const int h  = (bx >> 5) % 12;
    const int b  = bx / 384;
    const int tid = threadIdx.x;

    const int ng = tid >> 2;
    const int mg = tid & 3;
    const int n0 = ng * 4, m0 = mg * 8;
    const int kg = tid >> 5;
    const int lane = tid & 31;
    const int dg = lane >> 2;
    const int mq = lane & 3;
    const int rd = tid >> 3;
    const int rm = (tid & 7) * 4;

    const float scale1 = rsqrtf(frx[h] * 32.0f);
    const float scale2 = rsqrtf(fra[h] * 256.0f);

    float v2[4][8];
    float v3[4];
#pragma unroll
    for (int i = 0; i < 4; i++)
#pragma unroll
        for (int j = 0; j < 8; j++) v2[i][j] = 0.0f;
#pragma unroll
    for (int i = 0; i < 4; i++) v3[i] = 0.0f;

    for (int t = 0; t < 4; t++) {
        const int img = t * 4 + b;
        const float* ybase = g_y + ((size_t)img * 768 + h * 64) * 256;
#pragma unroll
        for (int r = 0; r < 8; r++) {
            int e = tid + 256 * r;
            int d = e >> 6, c4 = (e & 63) * 4;
            float4 w = *(const float4*)&ybase[d * 256 + c4];
            *(float4*)&y1s[d * 256 + c4] = make_float4(
                w.x * scale1, w.y * scale1, w.z * scale1, w.w * scale1);
        }
#pragma unroll
        for (int r = 0; r < 8; r++) {
            int e = tid + 256 * r;
            int d = e >> 6, c4 = (e & 63) * 4;
            float4 w = *(const float4*)&ybase[(32 + d) * 256 + c4];
            *(float4*)&y2s[d * 260 + c4] = make_float4(
                w.x * scale2, w.y * scale2, w.z * scale2, w.w * scale2);
        }
        {
            const float* xbase = g_xs + ((size_t)img * 384 + h * 32) * 1024 + mt * 32;
            int d = tid >> 3, c4 = (tid & 7) * 4;
            *(float4*)&xrs[d * 32 + c4] = *(const float4*)&xbase[d * 1024 + c4];
        }
        __syncthreads();

        // GEMM1
        u64 acc[4][4];
#pragma unroll
        for (int i = 0; i < 4; i++)
#pragma unroll
            for (int q = 0; q < 4; q++) acc[i][q] = pk2(v2[i][2 * q], v2[i][2 * q + 1]);
#pragma unroll 8
        for (int d = 0; d < 32; d++) {
            float4 a4 = *(const float4*)&y1s[d * 256 + n0];
            ulonglong2 x0 = *(const ulonglong2*)&xrs[d * 32 + m0];
            ulonglong2 x1 = *(const ulonglong2*)&xrs[d * 32 + m0 + 4];
            float av[4] = {a4.x, a4.y, a4.z, a4.w};
#pragma unroll
            for (int i = 0; i < 4; i++) {
                u64 ar = pk2(av[i], av[i]);
                acc[i][0] = ffma2(ar, x0.x, acc[i][0]);
                acc[i][1] = ffma2(ar, x0.y, acc[i][1]);
                acc[i][2] = ffma2(ar, x1.x, acc[i][2]);
                acc[i][3] = ffma2(ar, x1.y, acc[i][3]);
            }
        }
        // LIF2
#pragma unroll
        for (int i = 0; i < 4; i++) {
            float s[8];
#pragma unroll
            for (int q = 0; q < 4; q++) {
                float lo, hi;
                upk2(acc[i][q], lo, hi);
                lo *= 0.5f; hi *= 0.5f;
                s[2 * q]     = (lo >= 1.0f) ? 1.0f : 0.0f;
                s[2 * q + 1] = (hi >= 1.0f) ? 1.0f : 0.0f;
                v2[i][2 * q]     = (lo >= 1.0f) ? 0.0f : lo;
                v2[i][2 * q + 1] = (hi >= 1.0f) ? 0.0f : hi;
            }
            *(float4*)&ss[(n0 + i) * 36 + m0]     = make_float4(s[0], s[1], s[2], s[3]);
            *(float4*)&ss[(n0 + i) * 36 + m0 + 4] = make_float4(s[4], s[5], s[6], s[7]);
        }
        __syncthreads();

        // GEMM2 (ksplit 8)
        u64 acc2[4][4];
#pragma unroll
        for (int i = 0; i < 4; i++)
#pragma unroll
            for (int q = 0; q < 4; q++) acc2[i][q] = 0ull;
#pragma unroll
        for (int nn = 0; nn < 32; nn += 4) {
            int n = kg * 32 + nn;
            float4 b0 = *(const float4*)&y2s[(dg +  0) * 260 + n];
            float4 b1 = *(const float4*)&y2s[(dg +  8) * 260 + n];
            float4 b2 = *(const float4*)&y2s[(dg + 16) * 260 + n];
            float4 b3 = *(const float4*)&y2s[(dg + 24) * 260 + n];
            float bv[4][4] = {{b0.x, b0.y, b0.z, b0.w}, {b1.x, b1.y, b1.z, b1.w},
                              {b2.x, b2.y, b2.z, b2.w}, {b3.x, b3.y, b3.z, b3.w}};
#pragma unroll
            for (int j = 0; j < 4; j++) {
                ulonglong2 s0 = *(const ulonglong2*)&ss[(n + j) * 36 + mq * 8];
                ulonglong2 s1 = *(const ulonglong2*)&ss[(n + j) * 36 + mq * 8 + 4];
#pragma unroll
                for (int i = 0; i < 4; i++) {
                    u64 ar = pk2(bv[i][j], bv[i][j]);
                    acc2[i][0] = ffma2(ar, s0.x, acc2[i][0]);
                    acc2[i][1] = ffma2(ar, s0.y, acc2[i][1]);
                    acc2[i][2] = ffma2(ar, s1.x, acc2[i][2]);
                    acc2[i][3] = ffma2(ar, s1.y, acc2[i][3]);
                }
            }
        }
        __syncthreads();
#pragma unroll
        for (int i = 0; i < 4; i++) {
            float* dst = &sp[kg * 1152 + (dg + 8 * i) * 36 + mq * 8];
            *(ulonglong2*)dst       = make_ulonglong2(acc2[i][0], acc2[i][1]);
            *(ulonglong2*)(dst + 4) = make_ulonglong2(acc2[i][2], acc2[i][3]);
        }
        __syncthreads();

        // reduce + LIF3 + bf16 spike store
        float4 sum = make_float4(v3[0], v3[1], v3[2], v3[3]);
#pragma unroll
        for (int k = 0; k < 8; k++) {
            float4 p = *(const float4*)&sp[k * 1152 + rd * 36 + rm];
            sum.x += p.x; sum.y += p.y; sum.z += p.z; sum.w += p.w;
        }
        sum.x *= 0.5f; sum.y *= 0.5f; sum.z *= 0.5f; sum.w *= 0.5f;
        ushort4 sb;
        sb.x = (sum.x >= 1.0f) ? 0x3F80 : 0; v3[0] = (sum.x >= 1.0f) ? 0.0f : sum.x;
        sb.y = (sum.y >= 1.0f) ? 0x3F80 : 0; v3[1] = (sum.y >= 1.0f) ? 0.0f : sum.y;
        sb.z = (sum.z >= 1.0f) ? 0x3F80 : 0; v3[2] = (sum.z >= 1.0f) ? 0.0f : sum.z;
        sb.w = (sum.w >= 1.0f) ? 0x3F80 : 0; v3[3] = (sum.w >= 1.0f) ? 0.0f : sum.w;
        *(ushort4*)&g_sp3b[((size_t)img * 384 + h * 32 + rd) * 1024 + mt * 32 + rm] = sb;
        __syncthreads();
    }
}

// ============================================================
// Kernel T: transpose bf16 spikes [c][hw] -> [hw][c] per img
// ============================================================
__global__ void __launch_bounds__(256) transpose_sp3_kernel() {
    __shared__ u16 ts[64][72];
    int bx = blockIdx.x;
    int img = bx / 96;
    int r = bx % 96;
    int c0 = (r / 16) * 64;
    int hw0 = (r % 16) * 64;
    int tid = threadIdx.x;
#pragma unroll
    for (int it = 0; it < 4; it++) {
        int e = tid + 256 * it;
        int row = e >> 4, q = e & 15;
        u64 v = *(const u64*)&g_sp3b[((size_t)img * 384 + c0 + row) * 1024 + hw0 + q * 4];
        *(u64*)&ts[row][q * 4] = v;
    }
    __syncthreads();
#pragma unroll
    for (int it = 0; it < 4; it++) {
        int e = tid + 256 * it;
        int orow = e >> 4, q = e & 15;
        u64 v = (u64)ts[q * 4 + 0][orow]
              | ((u64)ts[q * 4 + 1][orow] << 16)
              | ((u64)ts[q * 4 + 2][orow] << 32)
              | ((u64)ts[q * 4 + 3][orow] << 48);
        *(u64*)&g_sp3T[((size_t)img * 1024 + hw0 + orow) * 384 + c0 + q * 4] = v;
    }
}

// ============================================================
// Kernel D: proj as mma.sync GEMM + BN2 + residual.
// CTA tile 128(o) x 128(hw), K=384 in 12 chunks of 32.
// grid 384, 256 thr, 80KB smem. cp.async + ldmatrix.
// ============================================================
__global__ void __launch_bounds__(256) proj_mma_kernel(
    const float* __restrict__ g2, const float* __restrict__ b2v,
    const float* __restrict__ x, float* __restrict__ out)
{
    extern __shared__ u32 smu[];
    const u32 sbase = smem_u32(smu);
    const int tid = threadIdx.x;
    const int wid = tid >> 5, lane = tid & 31;
    const int g = lane >> 2, t = lane & 3;
    const int wm = wid >> 2, wn = wid & 3;
    const int bx = blockIdx.x;
    const int ot = bx >> 7;
    const int nt = bx & 127;
    const int obase = ot * 128;
    const int img = nt >> 3;
    const int hw0 = (nt & 7) * 128;
    const u16* Asrc = g_wp3;
    const u16* Bsrc = g_sp3T + ((size_t)img * 1024 + hw0) * 384;

    float acc[4][4][4];
#pragma unroll
    for (int mt = 0; mt < 4; mt++)
#pragma unroll
        for (int ntt = 0; ntt < 4; ntt++)
#pragma unroll
            for (int q = 0; q < 4; q++) acc[mt][ntt][q] = 0.0f;

    auto ldChunk = [&](int c, int buf) {
        u32 sb = sbase + buf * 40960;
        int k0 = c * 32;
#pragma unroll
        for (int it = 0; it < 6; it++) {
            int e = tid + 256 * it;
            int j = e >> 9;
            int r = (e >> 2) & 127;
            int kg = e & 3;
            cp16(sb + (j * 2560 + r * 20 + kg * 4) * 4,
                 &Asrc[(size_t)j * 147456 + (size_t)(obase + r) * 384 + k0 + kg * 8]);
        }
#pragma unroll
        for (int it = 0; it < 2; it++) {
            int e = tid + 256 * it;
            int r = e >> 2, kg = e & 3;
            cp16(sb + (7680 + r * 20 + kg * 4) * 4,
                 &Bsrc[(size_t)r * 384 + k0 + kg * 8]);
        }
        CP_COMMIT();
    };

    const int aRow = wm * 64 + (lane & 15);
    const int aColw = ((lane >> 4) & 1) * 4;
    const int bRow = wn * 32 + ((lane >> 4) & 1) * 8 + (lane & 7);
    const int bColw = ((lane >> 3) & 1) * 4;

    ldChunk(0, 0);
    for (int c = 0; c < 12; c++) {
        int buf = c & 1;
        if (c + 1 < 12) { ldChunk(c + 1, buf ^ 1); CP_WAIT1(); }
        else            { CP_WAIT0(); }
        __syncthreads();
        u32 soff = sbase + buf * 40960;
#pragma unroll
        for (int k16 = 0; k16 < 2; k16++) {
            u32 bfr[4][2];
#pragma unroll
            for (int ntp = 0; ntp < 2; ntp++) {
                u32 addr = soff + ((7680 + (bRow + ntp * 16) * 20 + k16 * 8 + bColw) << 2);
                ldm_x4(bfr[2 * ntp][0], bfr[2 * ntp][1],
                       bfr[2 * ntp + 1][0], bfr[2 * ntp + 1][1], addr);
            }
#pragma unroll
            for (int j = 0; j < 3; j++) {
#pragma unroll
                for (int mt = 0; mt < 4; mt++) {
                    u32 addr = soff + ((j * 2560 + (aRow + mt * 16) * 20 + k16 * 8 + aColw) << 2);
                    u32 a0, a1, a2, a3;
                    ldm_x4(a0, a1, a2, a3, addr);
#pragma unroll
                    for (int ntt = 0; ntt < 4; ntt++)
                        mma16816(acc[mt][ntt][0], acc[mt][ntt][1],
                                 acc[mt][ntt][2], acc[mt][ntt][3],
                                 a0, a1, a2, a3, bfr[ntt][0], bfr[ntt][1]);
                }
            }
        }
        __syncthreads();
    }

    const float rs = rsqrtf(1.0f + EPSF);
#pragma unroll
    for (int mt = 0; mt < 4; mt++) {
        int o0 = obase + wm * 64 + mt * 16 + g;
        int o1 = o0 + 8;
        float bn0 = g2[o0] * rs, bt0 = b2v[o0];
        float bn1 = g2[o1] * rs, bt1 = b2v[o1];
#pragma unroll
        for (int ntt = 0; ntt < 4; ntt++) {
            int col = hw0 + wn * 32 + ntt * 8 + 2 * t;
            size_t i0 = ((size_t)img * 384 + o0) * 1024 + col;
            size_t i1 = ((size_t)img * 384 + o1) * 1024 + col;
            float2 x0 = *(const float2*)&x[i0];
            float2 x1 = *(const float2*)&x[i1];
            *(float2*)&out[i0] = make_float2(acc[mt][ntt][0] * bn0 + bt0 + x0.x,
                                             acc[mt][ntt][1] * bn0 + bt0 + x0.y);
            *(float2*)&out[i1] = make_float2(acc[mt][ntt][2] * bn1 + bt1 + x1.x,
                                             acc[mt][ntt][3] * bn1 + bt1 + x1.y);
        }
    }
}

// ============================================================
extern "C" void kernel_launch(void* const* d_in, const int* in_sizes, int n_in,
                              void* d_out, int out_size) {
    const float* x   = (const float*)d_in[0];
    const float* Wc  = (const float*)d_in[1];
    const float* g1  = (const float*)d_in[2];
    const float* b1  = (const float*)d_in[3];
    const float* Wp  = (const float*)d_in[4];
    const float* g2  = (const float*)d_in[5];
    const float* b2  = (const float*)d_in[6];
    const float* frx = (const float*)d_in[7];
    const float* fra = (const float*)d_in[8];
    float* out = (float*)d_out;

    const int smem_attn = 26752 * 4;   // 107,008 B
    const int smem_mma  = 81920;       // 2 x 40KB double buffer
    cudaFuncSetAttribute(attn_fused_kernel,
                         cudaFuncAttributeMaxDynamicSharedMemorySize, smem_attn);
    cudaFuncSetAttribute(conv_mma_kernel,
                         cudaFuncAttributeMaxDynamicSharedMemorySize, smem_mma);
    cudaFuncSetAttribute(proj_mma_kernel,
                         cudaFuncAttributeMaxDynamicSharedMemorySize, smem_mma);

    lif1_kernel<<<6144, 256>>>(x);
    im2col_kernel<<<6144, 256>>>();
    wsplit_kernel<<<5184, 256>>>(Wc, Wp);
    conv_mma_kernel<<<576, 256, smem_mma>>>();
    reduce_bn_kernel<<<3072, 256>>>(g1, b1);
    attn_fused_kernel<<<1536, 256, smem_attn>>>(frx, fra);
    transpose_sp3_kernel<<<1536, 256>>>();
    proj_mma_kernel<<<384, 256, smem_mma>>>(g2, b2, x, out);
}